// round 5
// baseline (speedup 1.0000x reference)
#include <cuda_runtime.h>

// Problem constants
#define NB 16
#define CI 64
#define CO 64
#define HH 128
#define WW 128
#define TH 16
#define TW 16
#define NTHREADS 256

// x chunking
#define XCH 8                      // channels per prefetched x chunk
#define XS_CH 324                  // 18*18 per channel
#define XS_CHUNK (XCH*XS_CH)       // 2592 floats
// smem layout (float offsets)
#define XS_OFF 0
#define XS_SZ (2*XS_CHUNK)         // 5184 (double buffered)
#define WS_OFF XS_SZ
#define WS_I_STRIDE 68             // padded, keeps float4 16B alignment
#define WS_M_STRIDE (64*WS_I_STRIDE)
#define WS_SZ (4*WS_M_STRIDE)      // 17408
#define AS_OFF (WS_OFF+WS_SZ)      // 22592
#define AS_SZ (4*4*256)            // 4096: A[j<4][m<4][256 pix]
#define SMEM_FLOATS (AS_OFF+AS_SZ) // 26688
#define SMEM_BYTES (SMEM_FLOATS*4) // 106752 B -> 2 CTAs/SM

__device__ __forceinline__ unsigned long long pack2(float lo, float hi) {
    unsigned long long r;
    asm("mov.b64 %0, {%1, %2};" : "=l"(r) : "f"(lo), "f"(hi));
    return r;
}
__device__ __forceinline__ void unpack2(unsigned long long v, float& lo, float& hi) {
    asm("mov.b64 {%0, %1}, %2;" : "=f"(lo), "=f"(hi) : "l"(v));
}
__device__ __forceinline__ void fma2(unsigned long long& d, unsigned long long a, unsigned long long b) {
    asm("fma.rn.f32x2 %0, %1, %2, %0;" : "+l"(d) : "l"(a), "l"(b));
}

__device__ __forceinline__ void load_chunk_async(const float* __restrict__ xb, int ch, int buf,
                                                 int h0, int w0, int tid, unsigned dbase0) {
    const int ic0 = ch * XCH;
    unsigned dbase = dbase0 + (unsigned)(buf * XS_CHUNK) * 4u;
    #pragma unroll 3
    for (int e = tid; e < XS_CHUNK; e += NTHREADS) {
        int j   = e / XS_CH;
        int rem = e - j * XS_CH;
        int r   = rem / 18;
        int c   = rem - r * 18;
        int gh = h0 - 1 + r, gw = w0 - 1 + c;
        bool v = ((unsigned)gh < (unsigned)HH) && ((unsigned)gw < (unsigned)WW);
        const float* src = v ? (xb + ((size_t)(ic0 + j) * HH + gh) * WW + gw) : xb;
        int sz = v ? 4 : 0;
        asm volatile("cp.async.ca.shared.global [%0], [%1], 4, %2;"
                     :: "r"(dbase + (unsigned)e * 4u), "l"(src), "r"(sz));
    }
}

__global__ __launch_bounds__(NTHREADS, 2)
void steered_kernel(const float* __restrict__ x, const float* __restrict__ theta,
                    const float* __restrict__ wts, const float* __restrict__ bias,
                    float* __restrict__ out) {
    extern __shared__ float sm[];
    const unsigned smem_u32 = (unsigned)__cvta_generic_to_shared(sm);
    const int tid = threadIdx.x;
    const int n  = blockIdx.z;
    const int h0 = blockIdx.y * TH;
    const int w0 = blockIdx.x * TW;
    const float* xb = x + (size_t)n * CI * HH * WW;

    // ---- prefetch x chunks 0 and 1 ----
    load_chunk_async(xb, 0, 0, h0, w0, tid, smem_u32);
    asm volatile("cp.async.commit_group;" ::: "memory");
    load_chunk_async(xb, 1, 1, h0, w0, tid, smem_u32);
    asm volatile("cp.async.commit_group;" ::: "memory");

    // ---- weights (O,I,4) -> Ws[m][i][o] (overlaps cp.async) ----
    for (int e = tid; e < CO * CI; e += NTHREADS) {
        float4 v = ((const float4*)wts)[e];      // wts[o][i][0..3]
        int o = e >> 6, i = e & 63;
        float* p = sm + WS_OFF + i * WS_I_STRIDE + o;
        p[0]               = v.x;
        p[WS_M_STRIDE]     = v.y;
        p[2*WS_M_STRIDE]   = v.z;
        p[3*WS_M_STRIDE]   = v.w;
    }

    // ---- per-pixel harmonic coefficients (registers only) ----
    const int py = tid >> 4, px = tid & 15;
    float th = theta[((size_t)n * HH + (h0 + py)) * WW + (w0 + px)];
    float aang = 6.28318530717958647692f * th;
    float s1, c1;
    sincosf(aang, &s1, &c1);
    const float c2 = 2.f * c1 * c1 - 1.f;
    const float s2 = 2.f * s1 * c1;
    const float cps = c1 + s1, cms = c1 - s1;
    const int ctr = (py + 1) * 18 + (px + 1);

    const int lane = tid & 31;
    const int warp = tid >> 5;
    // warp blocking: 16 o x 128 pix per warp (4 o-blocks x 2 pix-blocks)
    const int o0 = (warp & 3) * 16;
    const int pb = (warp >> 2) * 128 + lane * 4;   // thread's 4 consecutive pixels

    unsigned long long acc[16][2];
    #pragma unroll
    for (int a_ = 0; a_ < 16; a_++) { acc[a_][0] = 0ull; acc[a_][1] = 0ull; }

    const float Q = 0.35355339059327376220f;  // 1/(2*sqrt(2))

    asm volatile("cp.async.wait_group 1;" ::: "memory");  // chunk 0 ready
    __syncthreads();

    for (int ch = 0; ch < 8; ch++) {
        const float* xsb = sm + XS_OFF + (ch & 1) * XS_CHUNK;
        #pragma unroll 1
        for (int sub = 0; sub < 2; sub++) {
            // ---- build A: 4 channels, per-pixel steered taps ----
            #pragma unroll
            for (int j = 0; j < 4; j++) {
                const float* xp = xsb + (sub * 4 + j) * XS_CH + ctr;
                float t0 = xp[-19], t1 = xp[-18], t2 = xp[-17];
                float t3 = xp[-1],  t4 = xp[0],   t5 = xp[1];
                float t6 = xp[17],  t7 = xp[18],  t8 = xp[19];
                float ring = ((t0 + t1) + (t2 + t3)) + ((t5 + t6) + (t7 + t8));
                float z2 = Q * (cps * (t8 - t0) + cms * (t2 - t6))
                         + 0.5f * (c1 * (t5 - t3) + s1 * (t7 - t1));
                float z3 = 0.5f * (s2 * ((t0 + t8) - (t2 + t6))
                                 + c2 * ((t3 + t5) - (t1 + t7)));
                float* Ap = sm + AS_OFF + j * 1024;
                Ap[tid]        = t4;        // m=0 center
                Ap[256 + tid]  = Q * ring;  // m=1 ring
                Ap[512 + tid]  = z2;        // m=2 k=1 steered
                Ap[768 + tid]  = z3;        // m=3 k=2 steered
            }
            __syncthreads();
            // prefetch chunk ch+2 into the buffer this iteration frees
            if (sub == 1 && ch < 6) {
                load_chunk_async(xb, ch + 2, ch & 1, h0, w0, tid, smem_u32);
                asm volatile("cp.async.commit_group;" ::: "memory");
            }
            // ---- GEMM over 16 k-values (4 ch x 4 m), 16o x 4pix per thread ----
            const int ic0 = ch * 8 + sub * 4;
            #pragma unroll
            for (int j = 0; j < 4; j++) {
                const float* Wj = sm + WS_OFF + (ic0 + j) * WS_I_STRIDE + o0;
                #pragma unroll
                for (int m = 0; m < 4; m++) {
                    const float* Ap = sm + AS_OFF + (j * 4 + m) * 256;
                    ulonglong2 av = *(const ulonglong2*)(Ap + pb);
                    const float* W = Wj + m * WS_M_STRIDE;
                    float4 wq0 = *(const float4*)(W);
                    float4 wq1 = *(const float4*)(W + 4);
                    float4 wq2 = *(const float4*)(W + 8);
                    float4 wq3 = *(const float4*)(W + 12);
                    unsigned long long t;
#define MO(oo, wv) \
                    t = pack2((wv), (wv)); \
                    fma2(acc[oo][0], av.x, t); fma2(acc[oo][1], av.y, t);
                    MO(0,  wq0.x) MO(1,  wq0.y) MO(2,  wq0.z) MO(3,  wq0.w)
                    MO(4,  wq1.x) MO(5,  wq1.y) MO(6,  wq1.z) MO(7,  wq1.w)
                    MO(8,  wq2.x) MO(9,  wq2.y) MO(10, wq2.z) MO(11, wq2.w)
                    MO(12, wq3.x) MO(13, wq3.y) MO(14, wq3.z) MO(15, wq3.w)
#undef MO
                }
            }
            if (sub == 1) {
                if (ch < 6) { asm volatile("cp.async.wait_group 1;" ::: "memory"); }
                else        { asm volatile("cp.async.wait_group 0;" ::: "memory"); }
            }
            __syncthreads();
        }
    }

    // ---- epilogue: bias + store (4 consecutive px per thread -> float4) ----
    const int pyq = pb >> 4, pxq = pb & 15;
    float* op = out + (size_t)n * CO * HH * WW + (size_t)(h0 + pyq) * WW + (w0 + pxq);
    #pragma unroll
    for (int oo = 0; oo < 16; oo++) {
        int o = o0 + oo;
        float b = __ldg(bias + o);
        float4 r;
        float lo, hi;
        unpack2(acc[oo][0], lo, hi); r.x = lo + b; r.y = hi + b;
        unpack2(acc[oo][1], lo, hi); r.z = lo + b; r.w = hi + b;
        *(float4*)(op + (size_t)o * (HH * WW)) = r;
    }
}

extern "C" void kernel_launch(void* const* d_in, const int* in_sizes, int n_in,
                              void* d_out, int out_size) {
    const float* x     = (const float*)d_in[0];
    const float* theta = (const float*)d_in[1];
    const float* wts   = (const float*)d_in[2];
    const float* bias  = (const float*)d_in[3];
    float* out = (float*)d_out;

    cudaFuncSetAttribute(steered_kernel,
                         cudaFuncAttributeMaxDynamicSharedMemorySize, SMEM_BYTES);
    dim3 grid(WW / TW, HH / TH, NB);
    steered_kernel<<<grid, NTHREADS, SMEM_BYTES>>>(x, theta, wts, bias, out);
}

// round 6
// speedup vs baseline: 1.3751x; 1.3751x over previous
#include <cuda_runtime.h>
#include <cstdint>

#define NB 16
#define CI 64
#define CO 64
#define HH 128
#define WW 128
#define TH 16
#define TW 16
#define NTHREADS 256
#define NCHUNK 16
#define XS_CH 324
#define XS_CHUNK (4*XS_CH)          // 1296 floats: 4 channels with halo

// smem byte offsets (all GEMM bases 128B-aligned)
#define XB_OFF 0
#define XB_BYTES (2*XS_CHUNK*4)     // 10368
#define WH_OFF 10368                // W hi: 16 chunks * 64o * 32B = 32768
#define WL_OFF (WH_OFF+32768)       // 43136
#define AH_OFF (WL_OFF+32768)       // 75904: A hi, 2 bufs * 8192
#define AL_OFF (AH_OFF+16384)       // 92288
#define SMEM_BYTES (AL_OFF+16384)   // 108672 -> 2 CTAs/SM

// k-major 32B rows; 16B-unit XOR swizzle -> conflict-free ldmatrix/STS
#define SWZ(row, half) (((((row)*2+(half)) ^ (((row)>>2)&1)))*16)

__device__ __forceinline__ uint32_t f2bf(float f){
    uint32_t u = __float_as_uint(f);
    return (u + 0x7FFFu + ((u>>16)&1u)) >> 16;   // rn-even
}
__device__ __forceinline__ uint32_t packbf(float a, float b, float& la, float& lb){
    uint32_t ba = f2bf(a), bb = f2bf(b);
    la = a - __uint_as_float(ba<<16);
    lb = b - __uint_as_float(bb<<16);
    return ba | (bb<<16);
}
__device__ __forceinline__ uint32_t pbf(float a, float b){
    return f2bf(a) | (f2bf(b)<<16);
}
__device__ __forceinline__ void ldm4(uint32_t* r, uint32_t addr){
    asm volatile("ldmatrix.sync.aligned.m8n8.x4.shared.b16 {%0,%1,%2,%3}, [%4];"
                 : "=r"(r[0]), "=r"(r[1]), "=r"(r[2]), "=r"(r[3]) : "r"(addr));
}
__device__ __forceinline__ void mma16816(float* d, const uint32_t* a, uint32_t b0, uint32_t b1){
    asm volatile("mma.sync.aligned.m16n8k16.row.col.f32.bf16.bf16.f32 "
                 "{%0,%1,%2,%3}, {%4,%5,%6,%7}, {%8,%9}, {%0,%1,%2,%3};"
                 : "+f"(d[0]), "+f"(d[1]), "+f"(d[2]), "+f"(d[3])
                 : "r"(a[0]), "r"(a[1]), "r"(a[2]), "r"(a[3]), "r"(b0), "r"(b1));
}

__device__ __forceinline__ void load_chunk_async(const float* __restrict__ xb, int ch, int buf,
                                                 int h0, int w0, int tid, unsigned sb){
    unsigned dbase = sb + (unsigned)XB_OFF + (unsigned)(buf*XS_CHUNK)*4u;
    const int ic0 = ch*4;
    #pragma unroll 3
    for (int e = tid; e < XS_CHUNK; e += NTHREADS){
        int j = e / XS_CH; int rem = e - j*XS_CH;
        int r = rem/18; int c = rem - r*18;
        int gh = h0-1+r, gw = w0-1+c;
        bool v = ((unsigned)gh < (unsigned)HH) && ((unsigned)gw < (unsigned)WW);
        const float* src = v ? (xb + ((size_t)(ic0+j)*HH + gh)*WW + gw) : xb;
        int sz = v ? 4 : 0;
        asm volatile("cp.async.ca.shared.global [%0], [%1], 4, %2;"
                     :: "r"(dbase + (unsigned)e*4u), "l"(src), "r"(sz));
    }
}

__global__ __launch_bounds__(NTHREADS, 2)
void steered_mma(const float* __restrict__ x, const float* __restrict__ theta,
                 const float* __restrict__ wts, const float* __restrict__ bias,
                 float* __restrict__ out)
{
    extern __shared__ float smf[];
    char* sm = (char*)smf;
    const unsigned sb = (unsigned)__cvta_generic_to_shared(sm);
    const int tid = threadIdx.x;
    const int lane = tid & 31, warp = tid >> 5;
    const int n = blockIdx.z, h0 = blockIdx.y*TH, w0 = blockIdx.x*TW;
    const float* xb = x + (size_t)n*CI*HH*WW;

    // prefetch x chunks 0,1
    load_chunk_async(xb, 0, 0, h0, w0, tid, sb);
    asm volatile("cp.async.commit_group;" ::: "memory");
    load_chunk_async(xb, 1, 1, h0, w0, tid, sb);
    asm volatile("cp.async.commit_group;" ::: "memory");

    // ---- W preprocessing: wts[o][i][4] -> Wt[chunk][o][k16] bf16 hi/lo, swizzled ----
    #pragma unroll 4
    for (int t = 0; t < 16; t++){
        int e = tid + t*256;
        int o = e & 63, i = e >> 6;
        float4 v = ((const float4*)wts)[o*64 + i];     // w[o][i][0..3]
        int cc = i >> 2, j = i & 3;
        float l0, l1, l2, l3;
        uint32_t h0u = packbf(v.x, v.y, l0, l1);
        uint32_t h1u = packbf(v.z, v.w, l2, l3);
        int off = cc*2048 + SWZ(o, (j>>1)) + (j&1)*8;
        *(uint2*)(sm + WH_OFF + off) = make_uint2(h0u, h1u);
        *(uint2*)(sm + WL_OFF + off) = make_uint2(pbf(l0, l1), pbf(l2, l3));
    }

    // ---- per-pixel harmonics ----
    const int py = tid >> 4, px = tid & 15;
    float th = theta[((size_t)n*HH + (h0+py))*WW + (w0+px)];
    float s1, c1;
    sincosf(6.28318530717958647692f * th, &s1, &c1);
    const float c2 = 2.f*c1*c1 - 1.f, s2 = 2.f*s1*c1;
    const float cps = c1 + s1, cms = c1 - s1;
    const int ctr = py*18 + px + 19;             // (py+1)*18 + (px+1)
    const float Q = 0.35355339059327376220f;     // 1/(2*sqrt(2))

    // ---- per-lane ldmatrix swizzle offsets ----
    // A (m16k16): row = m0 + (lane&15), half = lane>>4
    uint32_t aswz0 = SWZ(warp*32 +      (lane & 15), (lane >> 4));
    uint32_t aswz1 = SWZ(warp*32 + 16 + (lane & 15), (lane >> 4));
    // W (n-pair): o_local = np*16 + (lane&7) + (lane>=16 ? 8:0), half = (lane>>3)&1
    const int olc = (lane & 7) + ((lane >> 4) << 3);
    const int whalf = (lane >> 3) & 1;
    uint32_t wswz[4];
    #pragma unroll
    for (int np = 0; np < 4; np++) wswz[np] = SWZ(np*16 + olc, whalf);

    float acc[2][8][4];
    #pragma unroll
    for (int a = 0; a < 2; a++)
        #pragma unroll
        for (int b = 0; b < 8; b++)
            #pragma unroll
            for (int q = 0; q < 4; q++) acc[a][b][q] = 0.f;

    for (int c = 0; c < NCHUNK; c++){
        const int buf = c & 1;
        if (c < 15) asm volatile("cp.async.wait_group 1;" ::: "memory");
        else        asm volatile("cp.async.wait_group 0;" ::: "memory");
        __syncthreads();   // X(c) visible; A[buf] free (last read chunk c-2, fenced by c-1 barriers)

        // ---- build A chunk: pixel row tid, 4 channels x 4 harmonics, hi/lo bf16 ----
        {
            const float* xsb = smf + (XB_OFF/4) + buf*XS_CHUNK;
            uint32_t hu[8], lu[8];
            #pragma unroll
            for (int j = 0; j < 4; j++){
                const float* xp = xsb + j*XS_CH + ctr;
                float t0=xp[-19], t1=xp[-18], t2=xp[-17];
                float t3=xp[-1],  t4=xp[0],   t5=xp[1];
                float t6=xp[17],  t7=xp[18],  t8=xp[19];
                float ring = ((t0+t1)+(t2+t3)) + ((t5+t6)+(t7+t8));
                float z2 = Q*(cps*(t8-t0) + cms*(t2-t6)) + 0.5f*(c1*(t5-t3) + s1*(t7-t1));
                float z3 = 0.5f*(s2*((t0+t8)-(t2+t6)) + c2*((t3+t5)-(t1+t7)));
                float l0,l1,l2,l3;
                hu[j*2]   = packbf(t4,     Q*ring, l0, l1);
                hu[j*2+1] = packbf(z2,     z3,     l2, l3);
                lu[j*2]   = pbf(l0, l1);
                lu[j*2+1] = pbf(l2, l3);
            }
            char* ah = sm + AH_OFF + buf*8192;
            char* al = sm + AL_OFF + buf*8192;
            *(uint4*)(ah + SWZ(tid,0)) = make_uint4(hu[0],hu[1],hu[2],hu[3]);
            *(uint4*)(ah + SWZ(tid,1)) = make_uint4(hu[4],hu[5],hu[6],hu[7]);
            *(uint4*)(al + SWZ(tid,0)) = make_uint4(lu[0],lu[1],lu[2],lu[3]);
            *(uint4*)(al + SWZ(tid,1)) = make_uint4(lu[4],lu[5],lu[6],lu[7]);
        }
        __syncthreads();   // A[buf] readable; X[buf] reusable

        if (c + 2 < NCHUNK){
            load_chunk_async(xb, c+2, buf, h0, w0, tid, sb);
            asm volatile("cp.async.commit_group;" ::: "memory");
        }

        // ---- tensor-core GEMM for this k16 chunk ----
        uint32_t ah_base = sb + AH_OFF + (unsigned)buf*8192u;
        uint32_t al_base = sb + AL_OFF + (unsigned)buf*8192u;
        uint32_t wh_base = sb + WH_OFF + (unsigned)c*2048u;
        uint32_t wl_base = sb + WL_OFF + (unsigned)c*2048u;
        uint32_t ahf[2][4], alf[2][4];
        ldm4(ahf[0], ah_base + aswz0);
        ldm4(ahf[1], ah_base + aswz1);
        ldm4(alf[0], al_base + aswz0);
        ldm4(alf[1], al_base + aswz1);
        #pragma unroll
        for (int np = 0; np < 4; np++){
            uint32_t bh[4], bl[4];
            ldm4(bh, wh_base + wswz[np]);
            ldm4(bl, wl_base + wswz[np]);
            #pragma unroll
            for (int s = 0; s < 2; s++){
                #pragma unroll
                for (int mt = 0; mt < 2; mt++){
                    float* d = acc[mt][np*2 + s];
                    mma16816(d, ahf[mt], bh[s*2], bh[s*2+1]);
                    mma16816(d, ahf[mt], bl[s*2], bl[s*2+1]);
                    mma16816(d, alf[mt], bh[s*2], bh[s*2+1]);
                }
            }
        }
    }

    // ---- epilogue: bias + store ----
    const int gr = lane >> 2, tg = lane & 3;
    float* ob = out + (size_t)n*CO*HH*WW;
    #pragma unroll
    for (int mt = 0; mt < 2; mt++){
        int p0 = warp*32 + mt*16 + gr;          // pixel rows p0, p0+8
        int py0 = p0 >> 4, px0 = p0 & 15;       // px0 = gr, px0+8 for second row
        size_t off0 = (size_t)(h0 + py0)*WW + (w0 + px0);
        size_t off1 = off0 + 8;
        #pragma unroll
        for (int nt = 0; nt < 8; nt++){
            int o = nt*8 + tg*2;
            float b0v = __ldg(bias + o);
            float b1v = __ldg(bias + o + 1);
            ob[(size_t)o*(HH*WW)     + off0] = acc[mt][nt][0] + b0v;
            ob[(size_t)(o+1)*(HH*WW) + off0] = acc[mt][nt][1] + b1v;
            ob[(size_t)o*(HH*WW)     + off1] = acc[mt][nt][2] + b0v;
            ob[(size_t)(o+1)*(HH*WW) + off1] = acc[mt][nt][3] + b1v;
        }
    }
}

extern "C" void kernel_launch(void* const* d_in, const int* in_sizes, int n_in,
                              void* d_out, int out_size) {
    const float* x     = (const float*)d_in[0];
    const float* theta = (const float*)d_in[1];
    const float* wts   = (const float*)d_in[2];
    const float* bias  = (const float*)d_in[3];
    float* out = (float*)d_out;

    cudaFuncSetAttribute(steered_mma,
                         cudaFuncAttributeMaxDynamicSharedMemorySize, SMEM_BYTES);
    dim3 grid(WW/TW, HH/TH, NB);
    steered_mma<<<grid, NTHREADS, SMEM_BYTES>>>(x, theta, wts, bias, out);
}

// round 7
// speedup vs baseline: 1.4680x; 1.0676x over previous
#include <cuda_runtime.h>
#include <cstdint>

#define NB 16
#define CI 64
#define CO 64
#define HH 128
#define WW 128
#define TH 16
#define TW 16
#define NTHREADS 256
#define NCHUNK 16
#define XS_CH 324
#define XS_CHUNK (4*XS_CH)          // 1296 floats: 4 channels with halo

// smem byte offsets (all GEMM bases 128B-aligned)
#define XB_OFF 0
#define XB_BYTES (2*XS_CHUNK*4)     // 10368
#define WH_OFF 10368                // W hi: 16 chunks * 64o * 32B = 32768
#define WL_OFF (WH_OFF+32768)       // 43136
#define AH_OFF (WL_OFF+32768)       // 75904: A hi, 2 bufs * 8192
#define AL_OFF (AH_OFF+16384)       // 92288
#define SMEM_BYTES (AL_OFF+16384)   // 108672 -> 2 CTAs/SM

// k-major 32B rows; 16B-unit XOR swizzle -> conflict-free ldmatrix/STS
#define SWZ(row, half) (((((row)*2+(half)) ^ (((row)>>2)&1)))*16)

// pack two f32 -> bf16x2 (lo = a, hi = b), rn-even, one HW instr
__device__ __forceinline__ uint32_t pbf(float a, float b){
    uint32_t pk;
    asm("cvt.rn.bf16x2.f32 %0, %1, %2;" : "=r"(pk) : "f"(b), "f"(a));
    return pk;
}
__device__ __forceinline__ uint32_t packbf(float a, float b, float& la, float& lb){
    uint32_t pk = pbf(a, b);
    la = a - __uint_as_float(pk << 16);
    lb = b - __uint_as_float(pk & 0xFFFF0000u);
    return pk;
}
__device__ __forceinline__ void ldm4(uint32_t* r, uint32_t addr){
    asm volatile("ldmatrix.sync.aligned.m8n8.x4.shared.b16 {%0,%1,%2,%3}, [%4];"
                 : "=r"(r[0]), "=r"(r[1]), "=r"(r[2]), "=r"(r[3]) : "r"(addr));
}
__device__ __forceinline__ void mma16816(float* d, const uint32_t* a, uint32_t b0, uint32_t b1){
    asm volatile("mma.sync.aligned.m16n8k16.row.col.f32.bf16.bf16.f32 "
                 "{%0,%1,%2,%3}, {%4,%5,%6,%7}, {%8,%9}, {%0,%1,%2,%3};"
                 : "+f"(d[0]), "+f"(d[1]), "+f"(d[2]), "+f"(d[3])
                 : "r"(a[0]), "r"(a[1]), "r"(a[2]), "r"(a[3]), "r"(b0), "r"(b1));
}

// per-chunk x loader with hoisted addressing: soff[k] < 0 marks OOB (zero-fill)
__device__ __forceinline__ void load_chunk_pre(const float* __restrict__ xb, int ch, int buf,
                                               int tid, unsigned sb, const int* soff){
    unsigned dbase = sb + (unsigned)XB_OFF + (unsigned)(buf*XS_CHUNK)*4u;
    const float* xc = xb + (size_t)(ch*4) * (HH*WW);
    #pragma unroll
    for (int k = 0; k < 6; k++){
        int e = tid + k*256;
        if (k < 5 || tid < (XS_CHUNK - 5*256)){
            int so = soff[k];
            const float* src = (so >= 0) ? (xc + so) : xb;
            int sz = (so >= 0) ? 4 : 0;
            asm volatile("cp.async.ca.shared.global [%0], [%1], 4, %2;"
                         :: "r"(dbase + (unsigned)e*4u), "l"(src), "r"(sz));
        }
    }
}

__global__ __launch_bounds__(NTHREADS, 2)
void steered_mma(const float* __restrict__ x, const float* __restrict__ theta,
                 const float* __restrict__ wts, const float* __restrict__ bias,
                 float* __restrict__ out)
{
    extern __shared__ float smf[];
    char* sm = (char*)smf;
    const unsigned sb = (unsigned)__cvta_generic_to_shared(sm);
    const int tid = threadIdx.x;
    const int lane = tid & 31, warp = tid >> 5;
    const int n = blockIdx.z, h0 = blockIdx.y*TH, w0 = blockIdx.x*TW;
    const float* xb = x + (size_t)n*CI*HH*WW;

    // ---- hoisted per-thread load addressing (chunk-invariant) ----
    int soff[6];
    #pragma unroll
    for (int k = 0; k < 6; k++){
        int e = tid + k*256;
        int j = e / XS_CH; int rem = e - j*XS_CH;
        int r = rem / 18;  int cc = rem - r*18;
        int gh = h0 - 1 + r, gw = w0 - 1 + cc;
        bool v = (e < XS_CHUNK) && ((unsigned)gh < (unsigned)HH) && ((unsigned)gw < (unsigned)WW);
        soff[k] = v ? (j*(HH*WW) + gh*WW + gw) : -1;
    }

    // prefetch x chunks 0,1
    load_chunk_pre(xb, 0, 0, tid, sb, soff);
    asm volatile("cp.async.commit_group;" ::: "memory");
    load_chunk_pre(xb, 1, 1, tid, sb, soff);
    asm volatile("cp.async.commit_group;" ::: "memory");

    // ---- W preprocessing: wts[o][i][4] -> Wt[chunk][o][k16] bf16 hi/lo, swizzled ----
    #pragma unroll 4
    for (int t = 0; t < 16; t++){
        int e = tid + t*256;
        int o = e & 63, i = e >> 6;
        float4 v = ((const float4*)wts)[o*64 + i];     // w[o][i][0..3]
        int cc = i >> 2, j = i & 3;
        float l0, l1, l2, l3;
        uint32_t h0u = packbf(v.x, v.y, l0, l1);
        uint32_t h1u = packbf(v.z, v.w, l2, l3);
        int off = cc*2048 + SWZ(o, (j>>1)) + (j&1)*8;
        *(uint2*)(sm + WH_OFF + off) = make_uint2(h0u, h1u);
        *(uint2*)(sm + WL_OFF + off) = make_uint2(pbf(l0, l1), pbf(l2, l3));
    }

    // ---- per-pixel harmonics ----
    const int py = tid >> 4, px = tid & 15;
    float th = theta[((size_t)n*HH + (h0+py))*WW + (w0+px)];
    float s1, c1;
    sincosf(6.28318530717958647692f * th, &s1, &c1);
    const float c2 = 2.f*c1*c1 - 1.f, s2 = 2.f*s1*c1;
    const float cps = c1 + s1, cms = c1 - s1;
    const int ctr = py*18 + px + 19;             // (py+1)*18 + (px+1)
    const float Q = 0.35355339059327376220f;     // 1/(2*sqrt(2))

    // ---- per-lane ldmatrix swizzle offsets ----
    uint32_t aswz0 = SWZ(warp*32 +      (lane & 15), (lane >> 4));
    uint32_t aswz1 = SWZ(warp*32 + 16 + (lane & 15), (lane >> 4));
    const int olc = (lane & 7) + ((lane >> 4) << 3);
    const int whalf = (lane >> 3) & 1;
    uint32_t wswz[4];
    #pragma unroll
    for (int np = 0; np < 4; np++) wswz[np] = SWZ(np*16 + olc, whalf);

    float acc[2][8][4];
    #pragma unroll
    for (int a = 0; a < 2; a++)
        #pragma unroll
        for (int b = 0; b < 8; b++)
            #pragma unroll
            for (int q = 0; q < 4; q++) acc[a][b][q] = 0.f;

    for (int c = 0; c < NCHUNK; c++){
        const int buf = c & 1;
        if (c < 15) asm volatile("cp.async.wait_group 1;" ::: "memory");
        else        asm volatile("cp.async.wait_group 0;" ::: "memory");
        __syncthreads();   // X(c) visible; A[buf] free

        // ---- build A chunk: pixel row tid, 4 channels x 4 harmonics, hi/lo bf16 ----
        {
            const float* xsb = smf + (XB_OFF/4) + buf*XS_CHUNK;
            uint32_t hu[8], lu[8];
            #pragma unroll
            for (int j = 0; j < 4; j++){
                const float* xp = xsb + j*XS_CH + ctr;
                float t0=xp[-19], t1=xp[-18], t2=xp[-17];
                float t3=xp[-1],  t4=xp[0],   t5=xp[1];
                float t6=xp[17],  t7=xp[18],  t8=xp[19];
                float ring = ((t0+t1)+(t2+t3)) + ((t5+t6)+(t7+t8));
                float z2 = Q*(cps*(t8-t0) + cms*(t2-t6)) + 0.5f*(c1*(t5-t3) + s1*(t7-t1));
                float z3 = 0.5f*(s2*((t0+t8)-(t2+t6)) + c2*((t3+t5)-(t1+t7)));
                float l0,l1,l2,l3;
                hu[j*2]   = packbf(t4,     Q*ring, l0, l1);
                hu[j*2+1] = packbf(z2,     z3,     l2, l3);
                lu[j*2]   = pbf(l0, l1);
                lu[j*2+1] = pbf(l2, l3);
            }
            char* ah = sm + AH_OFF + buf*8192;
            char* al = sm + AL_OFF + buf*8192;
            *(uint4*)(ah + SWZ(tid,0)) = make_uint4(hu[0],hu[1],hu[2],hu[3]);
            *(uint4*)(ah + SWZ(tid,1)) = make_uint4(hu[4],hu[5],hu[6],hu[7]);
            *(uint4*)(al + SWZ(tid,0)) = make_uint4(lu[0],lu[1],lu[2],lu[3]);
            *(uint4*)(al + SWZ(tid,1)) = make_uint4(lu[4],lu[5],lu[6],lu[7]);
        }
        __syncthreads();   // A[buf] readable; X[buf] reusable

        if (c + 2 < NCHUNK){
            load_chunk_pre(xb, c+2, buf, tid, sb, soff);
            asm volatile("cp.async.commit_group;" ::: "memory");
        }

        // ---- tensor-core GEMM for this k16 chunk ----
        uint32_t ah_base = sb + AH_OFF + (unsigned)buf*8192u;
        uint32_t al_base = sb + AL_OFF + (unsigned)buf*8192u;
        uint32_t wh_base = sb + WH_OFF + (unsigned)c*2048u;
        uint32_t wl_base = sb + WL_OFF + (unsigned)c*2048u;
        uint32_t ahf[2][4], alf[2][4];
        ldm4(ahf[0], ah_base + aswz0);
        ldm4(ahf[1], ah_base + aswz1);
        ldm4(alf[0], al_base + aswz0);
        ldm4(alf[1], al_base + aswz1);
        #pragma unroll
        for (int np = 0; np < 4; np++){
            uint32_t bh[4], bl[4];
            ldm4(bh, wh_base + wswz[np]);
            ldm4(bl, wl_base + wswz[np]);
            #pragma unroll
            for (int s = 0; s < 2; s++){
                #pragma unroll
                for (int mt = 0; mt < 2; mt++){
                    float* d = acc[mt][np*2 + s];
                    mma16816(d, ahf[mt], bh[s*2], bh[s*2+1]);
                    mma16816(d, ahf[mt], bl[s*2], bl[s*2+1]);
                    mma16816(d, alf[mt], bh[s*2], bh[s*2+1]);
                }
            }
        }
    }

    // ---- epilogue: bias + store ----
    const int gr = lane >> 2, tg = lane & 3;
    float* ob = out + (size_t)n*CO*HH*WW;
    #pragma unroll
    for (int mt = 0; mt < 2; mt++){
        int p0 = warp*32 + mt*16 + gr;          // pixel rows p0, p0+8
        int py0 = p0 >> 4, px0 = p0 & 15;
        size_t off0 = (size_t)(h0 + py0)*WW + (w0 + px0);
        size_t off1 = off0 + 8;
        #pragma unroll
        for (int nt = 0; nt < 8; nt++){
            int o = nt*8 + tg*2;
            float b0v = __ldg(bias + o);
            float b1v = __ldg(bias + o + 1);
            ob[(size_t)o*(HH*WW)     + off0] = acc[mt][nt][0] + b0v;
            ob[(size_t)(o+1)*(HH*WW) + off0] = acc[mt][nt][1] + b1v;
            ob[(size_t)o*(HH*WW)     + off1] = acc[mt][nt][2] + b0v;
            ob[(size_t)(o+1)*(HH*WW) + off1] = acc[mt][nt][3] + b1v;
        }
    }
}

extern "C" void kernel_launch(void* const* d_in, const int* in_sizes, int n_in,
                              void* d_out, int out_size) {
    const float* x     = (const float*)d_in[0];
    const float* theta = (const float*)d_in[1];
    const float* wts   = (const float*)d_in[2];
    const float* bias  = (const float*)d_in[3];
    float* out = (float*)d_out;

    cudaFuncSetAttribute(steered_mma,
                         cudaFuncAttributeMaxDynamicSharedMemorySize, SMEM_BYTES);
    dim3 grid(WW/TW, HH/TH, NB);
    steered_mma<<<grid, NTHREADS, SMEM_BYTES>>>(x, theta, wts, bias, out);
}

// round 8
// speedup vs baseline: 1.6620x; 1.1321x over previous
#include <cuda_runtime.h>
#include <cstdint>

#define NB 16
#define CI 64
#define CO 64
#define HH 128
#define WW 128
#define TH 16
#define TW 16
#define NTHREADS 256
#define NCHUNK 16
#define XS_CH 324
#define XS_CHUNK (4*XS_CH)          // 1296 floats: 4 channels with halo

// smem byte offsets (GEMM bases 128B-aligned)
#define XB_OFF 0                    // 3 bufs * 5184 = 15552, pad to 15616
#define WH_OFF 15616                // W hi: 16 chunks * 64o * 32B = 32768
#define WL_OFF (WH_OFF+32768)       // 48384
#define AH_OFF (WL_OFF+32768)       // 81152: single A buffer (warp-local)
#define AL_OFF (AH_OFF+8192)        // 89344
#define SMEM_BYTES (AL_OFF+8192)    // 97536 -> 2 CTAs/SM

// k-major 32B rows; 16B-unit XOR swizzle -> conflict-free ldmatrix/STS
#define SWZ(row, half) (((((row)*2+(half)) ^ (((row)>>2)&1)))*16)

// pack two f32 -> bf16x2 (lo = a, hi = b), rn-even, one HW instr
__device__ __forceinline__ uint32_t pbf(float a, float b){
    uint32_t pk;
    asm("cvt.rn.bf16x2.f32 %0, %1, %2;" : "=r"(pk) : "f"(b), "f"(a));
    return pk;
}
__device__ __forceinline__ uint32_t packbf(float a, float b, float& la, float& lb){
    uint32_t pk = pbf(a, b);
    la = a - __uint_as_float(pk << 16);
    lb = b - __uint_as_float(pk & 0xFFFF0000u);
    return pk;
}
__device__ __forceinline__ void ldm4(uint32_t* r, uint32_t addr){
    asm volatile("ldmatrix.sync.aligned.m8n8.x4.shared.b16 {%0,%1,%2,%3}, [%4];"
                 : "=r"(r[0]), "=r"(r[1]), "=r"(r[2]), "=r"(r[3]) : "r"(addr));
}
__device__ __forceinline__ void mma16816(float* d, const uint32_t* a, uint32_t b0, uint32_t b1){
    asm volatile("mma.sync.aligned.m16n8k16.row.col.f32.bf16.bf16.f32 "
                 "{%0,%1,%2,%3}, {%4,%5,%6,%7}, {%8,%9}, {%0,%1,%2,%3};"
                 : "+f"(d[0]), "+f"(d[1]), "+f"(d[2]), "+f"(d[3])
                 : "r"(a[0]), "r"(a[1]), "r"(a[2]), "r"(a[3]), "r"(b0), "r"(b1));
}

// per-chunk x loader with hoisted addressing: soff[k] < 0 marks OOB (zero-fill)
__device__ __forceinline__ void load_chunk_pre(const float* __restrict__ xb, int ch, int buf,
                                               int tid, unsigned sb, const int* soff){
    unsigned dbase = sb + (unsigned)XB_OFF + (unsigned)(buf*XS_CHUNK)*4u;
    const float* xc = xb + (size_t)(ch*4) * (HH*WW);
    #pragma unroll
    for (int k = 0; k < 6; k++){
        int e = tid + k*256;
        if (k < 5 || tid < (XS_CHUNK - 5*256)){
            int so = soff[k];
            const float* src = (so >= 0) ? (xc + so) : xb;
            int sz = (so >= 0) ? 4 : 0;
            asm volatile("cp.async.ca.shared.global [%0], [%1], 4, %2;"
                         :: "r"(dbase + (unsigned)e*4u), "l"(src), "r"(sz));
        }
    }
}

__global__ __launch_bounds__(NTHREADS, 2)
void steered_mma(const float* __restrict__ x, const float* __restrict__ theta,
                 const float* __restrict__ wts, const float* __restrict__ bias,
                 float* __restrict__ out)
{
    extern __shared__ float smf[];
    char* sm = (char*)smf;
    const unsigned sb = (unsigned)__cvta_generic_to_shared(sm);
    const int tid = threadIdx.x;
    const int lane = tid & 31, warp = tid >> 5;
    const int n = blockIdx.z, h0 = blockIdx.y*TH, w0 = blockIdx.x*TW;
    const float* xb = x + (size_t)n*CI*HH*WW;

    // ---- hoisted per-thread load addressing (chunk-invariant) ----
    int soff[6];
    #pragma unroll
    for (int k = 0; k < 6; k++){
        int e = tid + k*256;
        int j = e / XS_CH; int rem = e - j*XS_CH;
        int r = rem / 18;  int cc = rem - r*18;
        int gh = h0 - 1 + r, gw = w0 - 1 + cc;
        bool v = (e < XS_CHUNK) && ((unsigned)gh < (unsigned)HH) && ((unsigned)gw < (unsigned)WW);
        soff[k] = v ? (j*(HH*WW) + gh*WW + gw) : -1;
    }

    // prefetch x chunks 0,1 into bufs 0,1
    load_chunk_pre(xb, 0, 0, tid, sb, soff);
    asm volatile("cp.async.commit_group;" ::: "memory");
    load_chunk_pre(xb, 1, 1, tid, sb, soff);
    asm volatile("cp.async.commit_group;" ::: "memory");

    // ---- W preprocessing: wts[o][i][4] -> Wt[chunk][o][k16] bf16 hi/lo, swizzled ----
    #pragma unroll 4
    for (int t = 0; t < 16; t++){
        int e = tid + t*256;
        int o = e & 63, i = e >> 6;
        float4 v = ((const float4*)wts)[o*64 + i];     // w[o][i][0..3]
        int cc = i >> 2, j = i & 3;
        float l0, l1, l2, l3;
        uint32_t h0u = packbf(v.x, v.y, l0, l1);
        uint32_t h1u = packbf(v.z, v.w, l2, l3);
        int off = cc*2048 + SWZ(o, (j>>1)) + (j&1)*8;
        *(uint2*)(sm + WH_OFF + off) = make_uint2(h0u, h1u);
        *(uint2*)(sm + WL_OFF + off) = make_uint2(pbf(l0, l1), pbf(l2, l3));
    }

    // ---- per-pixel harmonics ----
    const int py = tid >> 4, px = tid & 15;
    float th = theta[((size_t)n*HH + (h0+py))*WW + (w0+px)];
    float s1, c1;
    sincosf(6.28318530717958647692f * th, &s1, &c1);
    const float c2 = 2.f*c1*c1 - 1.f, s2 = 2.f*s1*c1;
    const float cps = c1 + s1, cms = c1 - s1;
    const int ctr = py*18 + px + 19;             // (py+1)*18 + (px+1)
    const float Q = 0.35355339059327376220f;     // 1/(2*sqrt(2))

    // ---- per-lane ldmatrix swizzle offsets ----
    uint32_t aswz0 = SWZ(warp*32 +      (lane & 15), (lane >> 4));
    uint32_t aswz1 = SWZ(warp*32 + 16 + (lane & 15), (lane >> 4));
    const int olc = (lane & 7) + ((lane >> 4) << 3);
    const int whalf = (lane >> 3) & 1;
    uint32_t wswz[4];
    #pragma unroll
    for (int np = 0; np < 4; np++) wswz[np] = SWZ(np*16 + olc, whalf);

    float acc[2][8][4];
    #pragma unroll
    for (int a = 0; a < 2; a++)
        #pragma unroll
        for (int b = 0; b < 8; b++)
            #pragma unroll
            for (int q = 0; q < 4; q++) acc[a][b][q] = 0.f;

    int xbuf = 0;                                  // c % 3
    for (int c = 0; c < NCHUNK; c++){
        if (c < 15) asm volatile("cp.async.wait_group 1;" ::: "memory");
        else        asm volatile("cp.async.wait_group 0;" ::: "memory");
        __syncthreads();   // X(c) visible everywhere; all warps done reading X(c-1)

        // prefetch X(c+2) into buf (c+2)%3 (conflicts only with retired X(c-1) reads)
        if (c + 2 < NCHUNK){
            int wb = xbuf + 2; if (wb >= 3) wb -= 3;
            load_chunk_pre(xb, c+2, wb, tid, sb, soff);
            asm volatile("cp.async.commit_group;" ::: "memory");
        }

        // ---- build A chunk (warp-local rows): 4 ch x 4 harmonics, hi/lo bf16 ----
        {
            const float* xsb = smf + xbuf*XS_CHUNK;
            uint32_t hu[8], lu[8];
            #pragma unroll
            for (int j = 0; j < 4; j++){
                const float* xp = xsb + j*XS_CH + ctr;
                float t0=xp[-19], t1=xp[-18], t2=xp[-17];
                float t3=xp[-1],  t4=xp[0],   t5=xp[1];
                float t6=xp[17],  t7=xp[18],  t8=xp[19];
                float ring = ((t0+t1)+(t2+t3)) + ((t5+t6)+(t7+t8));
                float z2 = Q*(cps*(t8-t0) + cms*(t2-t6)) + 0.5f*(c1*(t5-t3) + s1*(t7-t1));
                float z3 = 0.5f*(s2*((t0+t8)-(t2+t6)) + c2*((t3+t5)-(t1+t7)));
                float l0,l1,l2,l3;
                hu[j*2]   = packbf(t4,     Q*ring, l0, l1);
                hu[j*2+1] = packbf(z2,     z3,     l2, l3);
                lu[j*2]   = pbf(l0, l1);
                lu[j*2+1] = pbf(l2, l3);
            }
            char* ah = sm + AH_OFF;
            char* al = sm + AL_OFF;
            *(uint4*)(ah + SWZ(tid,0)) = make_uint4(hu[0],hu[1],hu[2],hu[3]);
            *(uint4*)(ah + SWZ(tid,1)) = make_uint4(hu[4],hu[5],hu[6],hu[7]);
            *(uint4*)(al + SWZ(tid,0)) = make_uint4(lu[0],lu[1],lu[2],lu[3]);
            *(uint4*)(al + SWZ(tid,1)) = make_uint4(lu[4],lu[5],lu[6],lu[7]);
        }
        __syncwarp();      // A rows are warp-private: STS -> ldmatrix visibility only

        // ---- tensor-core GEMM for this k16 chunk ----
        uint32_t ah_base = sb + AH_OFF;
        uint32_t al_base = sb + AL_OFF;
        uint32_t wh_base = sb + WH_OFF + (unsigned)c*2048u;
        uint32_t wl_base = sb + WL_OFF + (unsigned)c*2048u;
        uint32_t ahf[2][4], alf[2][4];
        ldm4(ahf[0], ah_base + aswz0);
        ldm4(ahf[1], ah_base + aswz1);
        ldm4(alf[0], al_base + aswz0);
        ldm4(alf[1], al_base + aswz1);
        #pragma unroll
        for (int np = 0; np < 4; np++){
            uint32_t bh[4], bl[4];
            ldm4(bh, wh_base + wswz[np]);
            ldm4(bl, wl_base + wswz[np]);
            #pragma unroll
            for (int s = 0; s < 2; s++){
                #pragma unroll
                for (int mt = 0; mt < 2; mt++){
                    float* d = acc[mt][np*2 + s];
                    mma16816(d, ahf[mt], bh[s*2], bh[s*2+1]);
                    mma16816(d, ahf[mt], bl[s*2], bl[s*2+1]);
                    mma16816(d, alf[mt], bh[s*2], bh[s*2+1]);
                }
            }
        }
        if (++xbuf == 3) xbuf = 0;
    }

    // ---- epilogue: bias + store ----
    const int gr = lane >> 2, tg = lane & 3;
    float* ob = out + (size_t)n*CO*HH*WW;
    #pragma unroll
    for (int mt = 0; mt < 2; mt++){
        int p0 = warp*32 + mt*16 + gr;          // pixel rows p0, p0+8
        int py0 = p0 >> 4, px0 = p0 & 15;
        size_t off0 = (size_t)(h0 + py0)*WW + (w0 + px0);
        size_t off1 = off0 + 8;
        #pragma unroll
        for (int nt = 0; nt < 8; nt++){
            int o = nt*8 + tg*2;
            float b0v = __ldg(bias + o);
            float b1v = __ldg(bias + o + 1);
            ob[(size_t)o*(HH*WW)     + off0] = acc[mt][nt][0] + b0v;
            ob[(size_t)(o+1)*(HH*WW) + off0] = acc[mt][nt][1] + b1v;
            ob[(size_t)o*(HH*WW)     + off1] = acc[mt][nt][2] + b0v;
            ob[(size_t)(o+1)*(HH*WW) + off1] = acc[mt][nt][3] + b1v;
        }
    }
}

extern "C" void kernel_launch(void* const* d_in, const int* in_sizes, int n_in,
                              void* d_out, int out_size) {
    const float* x     = (const float*)d_in[0];
    const float* theta = (const float*)d_in[1];
    const float* wts   = (const float*)d_in[2];
    const float* bias  = (const float*)d_in[3];
    float* out = (float*)d_out;

    cudaFuncSetAttribute(steered_mma,
                         cudaFuncAttributeMaxDynamicSharedMemorySize, SMEM_BYTES);
    dim3 grid(WW/TW, HH/TH, NB);
    steered_mma<<<grid, NTHREADS, SMEM_BYTES>>>(x, theta, wts, bias, out);
}

// round 9
// speedup vs baseline: 1.6868x; 1.0149x over previous
#include <cuda_runtime.h>
#include <cstdint>

#define NB 16
#define CI 64
#define CO 64
#define HH 128
#define WW 128
#define TH 16
#define TW 16
#define NTHREADS 256
#define NCHUNK 16

// staged x tile: per channel 18 rows x 24 floats ([w0-4, w0+20))
#define XROW 24
#define XS_CH (18*XROW)             // 432 floats
#define XS_CHUNK (4*XS_CH)          // 1728 floats per chunk
#define NSEG (4*18*6)               // 432 16B segments per chunk

// smem byte offsets (GEMM bases 128B-aligned)
#define XB_OFF 0                    // 3 bufs * 6912B = 20736
#define WH_OFF 20736                // W hi: 16 chunks * 64o * 32B = 32768
#define WL_OFF (WH_OFF+32768)       // 53504
#define AH_OFF (WL_OFF+32768)       // 86272: single A buffer (warp-local)
#define AL_OFF (AH_OFF+8192)        // 94464
#define SMEM_BYTES (AL_OFF+8192)    // 102656 -> 2 CTAs/SM

// k-major 32B rows; 16B-unit XOR swizzle -> conflict-free ldmatrix/STS
#define SWZ(row, half) (((((row)*2+(half)) ^ (((row)>>2)&1)))*16)

// pack two f32 -> bf16x2 (lo = a, hi = b), rn-even, one HW instr
__device__ __forceinline__ uint32_t pbf(float a, float b){
    uint32_t pk;
    asm("cvt.rn.bf16x2.f32 %0, %1, %2;" : "=r"(pk) : "f"(b), "f"(a));
    return pk;
}
__device__ __forceinline__ uint32_t packbf(float a, float b, float& la, float& lb){
    uint32_t pk = pbf(a, b);
    la = a - __uint_as_float(pk << 16);
    lb = b - __uint_as_float(pk & 0xFFFF0000u);
    return pk;
}
__device__ __forceinline__ void ldm4(uint32_t* r, uint32_t addr){
    asm volatile("ldmatrix.sync.aligned.m8n8.x4.shared.b16 {%0,%1,%2,%3}, [%4];"
                 : "=r"(r[0]), "=r"(r[1]), "=r"(r[2]), "=r"(r[3]) : "r"(addr));
}
__device__ __forceinline__ void mma16816(float* d, const uint32_t* a, uint32_t b0, uint32_t b1){
    asm volatile("mma.sync.aligned.m16n8k16.row.col.f32.bf16.bf16.f32 "
                 "{%0,%1,%2,%3}, {%4,%5,%6,%7}, {%8,%9}, {%0,%1,%2,%3};"
                 : "+f"(d[0]), "+f"(d[1]), "+f"(d[2]), "+f"(d[3])
                 : "r"(a[0]), "r"(a[1]), "r"(a[2]), "r"(a[3]), "r"(b0), "r"(b1));
}

// vectorized 16B x loader with hoisted addressing: soff<0 marks OOB (zero-fill)
__device__ __forceinline__ void load_chunk_vec(const float* __restrict__ xb, int ch, int buf,
                                               int tid, unsigned sb, const int* soff){
    unsigned dbase = sb + (unsigned)XB_OFF + (unsigned)buf*(XS_CHUNK*4u);
    const float* xc = xb + (size_t)(ch*4) * (HH*WW);
    #pragma unroll
    for (int k = 0; k < 2; k++){
        int e = tid + k*256;
        if (k == 0 || tid < (NSEG - 256)){
            int so = soff[k];
            const float* src = (so >= 0) ? (xc + so) : xb;
            int sz = (so >= 0) ? 16 : 0;
            asm volatile("cp.async.ca.shared.global [%0], [%1], 16, %2;"
                         :: "r"(dbase + (unsigned)e*16u), "l"(src), "r"(sz));
        }
    }
}

__global__ __launch_bounds__(NTHREADS, 2)
void steered_mma(const float* __restrict__ x, const float* __restrict__ theta,
                 const float* __restrict__ wts, const float* __restrict__ bias,
                 float* __restrict__ out)
{
    extern __shared__ float smf[];
    char* sm = (char*)smf;
    const unsigned sb = (unsigned)__cvta_generic_to_shared(sm);
    const int tid = threadIdx.x;
    const int lane = tid & 31, warp = tid >> 5;
    const int n = blockIdx.z, h0 = blockIdx.y*TH, w0 = blockIdx.x*TW;
    const float* xb = x + (size_t)n*CI*HH*WW;

    // ---- hoisted per-thread 16B-segment addressing (chunk-invariant) ----
    // e -> (channel j, row r, seg s): dst = j*432 + r*24 + s*4 floats
    // src = j*HW + (h0-1+r)*WW + (w0-4+s*4); OOB (row or seg) -> -1
    int soff[2];
    #pragma unroll
    for (int k = 0; k < 2; k++){
        int e = tid + k*256;
        int j = e / 108; int rem = e - j*108;
        int r = rem / 6;  int s = rem - r*6;
        int gh = h0 - 1 + r;
        int gw = w0 - 4 + s*4;
        bool v = (e < NSEG) && ((unsigned)gh < (unsigned)HH) && ((unsigned)gw < (unsigned)WW);
        soff[k] = v ? (j*(HH*WW) + gh*WW + gw) : -1;
    }

    // prefetch x chunks 0,1 into bufs 0,1
    load_chunk_vec(xb, 0, 0, tid, sb, soff);
    asm volatile("cp.async.commit_group;" ::: "memory");
    load_chunk_vec(xb, 1, 1, tid, sb, soff);
    asm volatile("cp.async.commit_group;" ::: "memory");

    // ---- W preprocessing: wts[o][i][4] -> Wt[chunk][o][k16] bf16 hi/lo, swizzled ----
    #pragma unroll 4
    for (int t = 0; t < 16; t++){
        int e = tid + t*256;
        int o = e & 63, i = e >> 6;
        float4 v = ((const float4*)wts)[o*64 + i];     // w[o][i][0..3]
        int cc = i >> 2, j = i & 3;
        float l0, l1, l2, l3;
        uint32_t h0u = packbf(v.x, v.y, l0, l1);
        uint32_t h1u = packbf(v.z, v.w, l2, l3);
        int off = cc*2048 + SWZ(o, (j>>1)) + (j&1)*8;
        *(uint2*)(sm + WH_OFF + off) = make_uint2(h0u, h1u);
        *(uint2*)(sm + WL_OFF + off) = make_uint2(pbf(l0, l1), pbf(l2, l3));
    }

    // ---- per-pixel harmonics ----
    const int py = tid >> 4, px = tid & 15;
    float th = theta[((size_t)n*HH + (h0+py))*WW + (w0+px)];
    float s1, c1;
    sincosf(6.28318530717958647692f * th, &s1, &c1);
    const float c2 = 2.f*c1*c1 - 1.f, s2 = 2.f*s1*c1;
    const float cps = c1 + s1, cms = c1 - s1;
    const int ctr = (py+1)*XROW + (px+4);        // center tap in staged tile
    const float Q = 0.35355339059327376220f;     // 1/(2*sqrt(2))

    // ---- per-lane ldmatrix swizzle offsets ----
    uint32_t aswz0 = SWZ(warp*32 +      (lane & 15), (lane >> 4));
    uint32_t aswz1 = SWZ(warp*32 + 16 + (lane & 15), (lane >> 4));
    const int olc = (lane & 7) + ((lane >> 4) << 3);
    const int whalf = (lane >> 3) & 1;
    uint32_t wswz[4];
    #pragma unroll
    for (int np = 0; np < 4; np++) wswz[np] = SWZ(np*16 + olc, whalf);

    float acc[2][8][4];
    #pragma unroll
    for (int a = 0; a < 2; a++)
        #pragma unroll
        for (int b = 0; b < 8; b++)
            #pragma unroll
            for (int q = 0; q < 4; q++) acc[a][b][q] = 0.f;

    int xbuf = 0;                                  // c % 3
    for (int c = 0; c < NCHUNK; c++){
        if (c < 15) asm volatile("cp.async.wait_group 1;" ::: "memory");
        else        asm volatile("cp.async.wait_group 0;" ::: "memory");
        __syncthreads();   // X(c) visible everywhere; all warps done reading X(c-1)

        // prefetch X(c+2) into buf (c+2)%3 (conflicts only with retired X(c-1) reads)
        if (c + 2 < NCHUNK){
            int wb = xbuf + 2; if (wb >= 3) wb -= 3;
            load_chunk_vec(xb, c+2, wb, tid, sb, soff);
            asm volatile("cp.async.commit_group;" ::: "memory");
        }

        // ---- build A chunk (warp-local rows): 4 ch x 4 harmonics, hi/lo bf16 ----
        {
            const float* xsb = smf + xbuf*XS_CHUNK;
            uint32_t hu[8], lu[8];
            #pragma unroll
            for (int j = 0; j < 4; j++){
                const float* xp = xsb + j*XS_CH + ctr;
                float t0=xp[-XROW-1], t1=xp[-XROW], t2=xp[-XROW+1];
                float t3=xp[-1],      t4=xp[0],     t5=xp[1];
                float t6=xp[XROW-1],  t7=xp[XROW],  t8=xp[XROW+1];
                float ring = ((t0+t1)+(t2+t3)) + ((t5+t6)+(t7+t8));
                float z2 = Q*(cps*(t8-t0) + cms*(t2-t6)) + 0.5f*(c1*(t5-t3) + s1*(t7-t1));
                float z3 = 0.5f*(s2*((t0+t8)-(t2+t6)) + c2*((t3+t5)-(t1+t7)));
                float l0,l1,l2,l3;
                hu[j*2]   = packbf(t4,     Q*ring, l0, l1);
                hu[j*2+1] = packbf(z2,     z3,     l2, l3);
                lu[j*2]   = pbf(l0, l1);
                lu[j*2+1] = pbf(l2, l3);
            }
            char* ah = sm + AH_OFF;
            char* al = sm + AL_OFF;
            *(uint4*)(ah + SWZ(tid,0)) = make_uint4(hu[0],hu[1],hu[2],hu[3]);
            *(uint4*)(ah + SWZ(tid,1)) = make_uint4(hu[4],hu[5],hu[6],hu[7]);
            *(uint4*)(al + SWZ(tid,0)) = make_uint4(lu[0],lu[1],lu[2],lu[3]);
            *(uint4*)(al + SWZ(tid,1)) = make_uint4(lu[4],lu[5],lu[6],lu[7]);
        }
        __syncwarp();      // A rows are warp-private: STS -> ldmatrix visibility only

        // ---- tensor-core GEMM for this k16 chunk ----
        uint32_t ah_base = sb + AH_OFF;
        uint32_t al_base = sb + AL_OFF;
        uint32_t wh_base = sb + WH_OFF + (unsigned)c*2048u;
        uint32_t wl_base = sb + WL_OFF + (unsigned)c*2048u;
        uint32_t ahf[2][4], alf[2][4];
        ldm4(ahf[0], ah_base + aswz0);
        ldm4(ahf[1], ah_base + aswz1);
        ldm4(alf[0], al_base + aswz0);
        ldm4(alf[1], al_base + aswz1);
        #pragma unroll
        for (int np = 0; np < 4; np++){
            uint32_t bh[4], bl[4];
            ldm4(bh, wh_base + wswz[np]);
            ldm4(bl, wl_base + wswz[np]);
            #pragma unroll
            for (int s = 0; s < 2; s++){
                #pragma unroll
                for (int mt = 0; mt < 2; mt++){
                    float* d = acc[mt][np*2 + s];
                    mma16816(d, ahf[mt], bh[s*2], bh[s*2+1]);
                    mma16816(d, ahf[mt], bl[s*2], bl[s*2+1]);
                    mma16816(d, alf[mt], bh[s*2], bh[s*2+1]);
                }
            }
        }
        if (++xbuf == 3) xbuf = 0;
    }

    // ---- epilogue: bias + store ----
    const int gr = lane >> 2, tg = lane & 3;
    float* ob = out + (size_t)n*CO*HH*WW;
    #pragma unroll
    for (int mt = 0; mt < 2; mt++){
        int p0 = warp*32 + mt*16 + gr;          // pixel rows p0, p0+8
        int py0 = p0 >> 4, px0 = p0 & 15;
        size_t off0 = (size_t)(h0 + py0)*WW + (w0 + px0);
        size_t off1 = off0 + 8;
        #pragma unroll
        for (int nt = 0; nt < 8; nt++){
            int o = nt*8 + tg*2;
            float b0v = __ldg(bias + o);
            float b1v = __ldg(bias + o + 1);
            ob[(size_t)o*(HH*WW)     + off0] = acc[mt][nt][0] + b0v;
            ob[(size_t)(o+1)*(HH*WW) + off0] = acc[mt][nt][1] + b1v;
            ob[(size_t)o*(HH*WW)     + off1] = acc[mt][nt][2] + b0v;
            ob[(size_t)(o+1)*(HH*WW) + off1] = acc[mt][nt][3] + b1v;
        }
    }
}

extern "C" void kernel_launch(void* const* d_in, const int* in_sizes, int n_in,
                              void* d_out, int out_size) {
    const float* x     = (const float*)d_in[0];
    const float* theta = (const float*)d_in[1];
    const float* wts   = (const float*)d_in[2];
    const float* bias  = (const float*)d_in[3];
    float* out = (float*)d_out;

    cudaFuncSetAttribute(steered_mma,
                         cudaFuncAttributeMaxDynamicSharedMemorySize, SMEM_BYTES);
    dim3 grid(WW/TW, HH/TH, NB);
    steered_mma<<<grid, NTHREADS, SMEM_BYTES>>>(x, theta, wts, bias, out);
}

// round 10
// speedup vs baseline: 1.8836x; 1.1167x over previous
#include <cuda_runtime.h>
#include <cstdint>

#define NB 16
#define CI 64
#define CO 64
#define HH 128
#define WW 128
#define TH 8
#define TW 32
#define NTHREADS 256
#define NCHUNK 16

// staged x tile: per channel 10 rows x 40 floats ([w0-4, w0+36))
#define XROW 40
#define XS_CH (10*XROW)             // 400 floats
#define XS_CHUNK (4*XS_CH)          // 1600 floats per chunk
#define NSEG (4*10*10)              // 400 16B segments per chunk

// smem byte offsets (GEMM bases 128B-aligned)
#define XB_OFF 0                    // 3 bufs * 6400B = 19200
#define WH_OFF 19200                // W hi: 16 chunks * 64o * 32B = 32768
#define WL_OFF (WH_OFF+32768)       // 51968
#define AH_OFF (WL_OFF+32768)       // 84736: single A buffer (warp-local)
#define AL_OFF (AH_OFF+8192)        // 92928
#define SMEM_BYTES (AL_OFF+8192)    // 101120 -> 2 CTAs/SM

// k-major 32B rows; 16B-unit XOR swizzle -> conflict-free ldmatrix/STS
#define SWZ(row, half) (((((row)*2+(half)) ^ (((row)>>2)&1)))*16)

// pack two f32 -> bf16x2 (lo = a, hi = b), rn-even, one HW instr
__device__ __forceinline__ uint32_t pbf(float a, float b){
    uint32_t pk;
    asm("cvt.rn.bf16x2.f32 %0, %1, %2;" : "=r"(pk) : "f"(b), "f"(a));
    return pk;
}
__device__ __forceinline__ uint32_t packbf(float a, float b, float& la, float& lb){
    uint32_t pk = pbf(a, b);
    la = a - __uint_as_float(pk << 16);
    lb = b - __uint_as_float(pk & 0xFFFF0000u);
    return pk;
}
__device__ __forceinline__ void ldm4(uint32_t* r, uint32_t addr){
    asm volatile("ldmatrix.sync.aligned.m8n8.x4.shared.b16 {%0,%1,%2,%3}, [%4];"
                 : "=r"(r[0]), "=r"(r[1]), "=r"(r[2]), "=r"(r[3]) : "r"(addr));
}
__device__ __forceinline__ void mma16816(float* d, const uint32_t* a, uint32_t b0, uint32_t b1){
    asm volatile("mma.sync.aligned.m16n8k16.row.col.f32.bf16.bf16.f32 "
                 "{%0,%1,%2,%3}, {%4,%5,%6,%7}, {%8,%9}, {%0,%1,%2,%3};"
                 : "+f"(d[0]), "+f"(d[1]), "+f"(d[2]), "+f"(d[3])
                 : "r"(a[0]), "r"(a[1]), "r"(a[2]), "r"(a[3]), "r"(b0), "r"(b1));
}

// vectorized 16B x loader with hoisted addressing: soff<0 marks OOB (zero-fill)
__device__ __forceinline__ void load_chunk_vec(const float* __restrict__ xb, int ch, int buf,
                                               int tid, unsigned sb, const int* soff){
    unsigned dbase = sb + (unsigned)XB_OFF + (unsigned)buf*(XS_CHUNK*4u);
    const float* xc = xb + (size_t)(ch*4) * (HH*WW);
    #pragma unroll
    for (int k = 0; k < 2; k++){
        int e = tid + k*256;
        if (k == 0 || tid < (NSEG - 256)){
            int so = soff[k];
            const float* src = (so >= 0) ? (xc + so) : xb;
            int sz = (so >= 0) ? 16 : 0;
            asm volatile("cp.async.cg.shared.global [%0], [%1], 16, %2;"
                         :: "r"(dbase + (unsigned)e*16u), "l"(src), "r"(sz));
        }
    }
}

__global__ __launch_bounds__(NTHREADS, 2)
void steered_mma(const float* __restrict__ x, const float* __restrict__ theta,
                 const float* __restrict__ wts, const float* __restrict__ bias,
                 float* __restrict__ out)
{
    extern __shared__ float smf[];
    char* sm = (char*)smf;
    const unsigned sb = (unsigned)__cvta_generic_to_shared(sm);
    const int tid = threadIdx.x;
    const int lane = tid & 31, warp = tid >> 5;
    const int n = blockIdx.z, h0 = blockIdx.y*TH, w0 = blockIdx.x*TW;
    const float* xb = x + (size_t)n*CI*HH*WW;

    // ---- hoisted per-thread 16B-segment addressing (chunk-invariant) ----
    // e -> (channel j, row r, seg s): dst = j*400 + r*40 + s*4 floats
    // src = j*HW + (h0-1+r)*WW + (w0-4+4s); OOB -> -1 (zero fill)
    int soff[2];
    #pragma unroll
    for (int k = 0; k < 2; k++){
        int e = tid + k*256;
        int j = e / 100; int rem = e - j*100;
        int r = rem / 10;  int s = rem - r*10;
        int gh = h0 - 1 + r;
        int gw = w0 - 4 + s*4;
        bool v = (e < NSEG) && ((unsigned)gh < (unsigned)HH) && ((unsigned)gw < (unsigned)WW);
        soff[k] = v ? (j*(HH*WW) + gh*WW + gw) : -1;
    }

    // prefetch x chunks 0,1 into bufs 0,1
    load_chunk_vec(xb, 0, 0, tid, sb, soff);
    asm volatile("cp.async.commit_group;" ::: "memory");
    load_chunk_vec(xb, 1, 1, tid, sb, soff);
    asm volatile("cp.async.commit_group;" ::: "memory");

    // ---- W preprocessing: wts[o][i][4] -> Wt[chunk][o][k16] bf16 hi/lo, swizzled ----
    #pragma unroll 4
    for (int t = 0; t < 16; t++){
        int e = tid + t*256;
        int o = e & 63, i = e >> 6;
        float4 v = ((const float4*)wts)[o*64 + i];     // w[o][i][0..3]
        int cc = i >> 2, j = i & 3;
        float l0, l1, l2, l3;
        uint32_t h0u = packbf(v.x, v.y, l0, l1);
        uint32_t h1u = packbf(v.z, v.w, l2, l3);
        int off = cc*2048 + SWZ(o, (j>>1)) + (j&1)*8;
        *(uint2*)(sm + WH_OFF + off) = make_uint2(h0u, h1u);
        *(uint2*)(sm + WL_OFF + off) = make_uint2(pbf(l0, l1), pbf(l2, l3));
    }

    // ---- per-pixel harmonics (pixel: row h0+py, col w0+px; py=tid>>5, px=tid&31) ----
    const int py = tid >> 5, px = tid & 31;
    float th = theta[((size_t)n*HH + (h0+py))*WW + (w0+px)];
    float s1, c1;
    sincosf(6.28318530717958647692f * th, &s1, &c1);
    const float c2 = 2.f*c1*c1 - 1.f, s2 = 2.f*s1*c1;
    const float cps = c1 + s1, cms = c1 - s1;
    const int ctr = (py+1)*XROW + (px+4);        // center tap in staged tile
    const float Q = 0.35355339059327376220f;     // 1/(2*sqrt(2))

    // ---- per-lane ldmatrix swizzle offsets ----
    uint32_t aswz0 = SWZ(warp*32 +      (lane & 15), (lane >> 4));
    uint32_t aswz1 = SWZ(warp*32 + 16 + (lane & 15), (lane >> 4));
    const int olc = (lane & 7) + ((lane >> 4) << 3);
    const int whalf = (lane >> 3) & 1;
    uint32_t wswz[4];
    #pragma unroll
    for (int np = 0; np < 4; np++) wswz[np] = SWZ(np*16 + olc, whalf);

    float acc[2][8][4];
    #pragma unroll
    for (int a = 0; a < 2; a++)
        #pragma unroll
        for (int b = 0; b < 8; b++)
            #pragma unroll
            for (int q = 0; q < 4; q++) acc[a][b][q] = 0.f;

    int xbuf = 0;                                  // c % 3
    for (int c = 0; c < NCHUNK; c++){
        if (c < 15) asm volatile("cp.async.wait_group 1;" ::: "memory");
        else        asm volatile("cp.async.wait_group 0;" ::: "memory");
        __syncthreads();   // X(c) visible everywhere; all warps done reading X(c-1)

        // prefetch X(c+2) into buf (c+2)%3 (conflicts only with retired X(c-1) reads)
        if (c + 2 < NCHUNK){
            int wb = xbuf + 2; if (wb >= 3) wb -= 3;
            load_chunk_vec(xb, c+2, wb, tid, sb, soff);
            asm volatile("cp.async.commit_group;" ::: "memory");
        }

        // ---- build A chunk (warp-local rows): 4 ch x 4 harmonics, hi/lo bf16 ----
        // warp = one image row of 32 pixels -> every tap LDS is conflict-free
        {
            const float* xsb = smf + xbuf*XS_CHUNK;
            uint32_t hu[8], lu[8];
            #pragma unroll
            for (int j = 0; j < 4; j++){
                const float* xp = xsb + j*XS_CH + ctr;
                float t0=xp[-XROW-1], t1=xp[-XROW], t2=xp[-XROW+1];
                float t3=xp[-1],      t4=xp[0],     t5=xp[1];
                float t6=xp[XROW-1],  t7=xp[XROW],  t8=xp[XROW+1];
                float ring = ((t0+t1)+(t2+t3)) + ((t5+t6)+(t7+t8));
                float z2 = Q*(cps*(t8-t0) + cms*(t2-t6)) + 0.5f*(c1*(t5-t3) + s1*(t7-t1));
                float z3 = 0.5f*(s2*((t0+t8)-(t2+t6)) + c2*((t3+t5)-(t1+t7)));
                float l0,l1,l2,l3;
                hu[j*2]   = packbf(t4,     Q*ring, l0, l1);
                hu[j*2+1] = packbf(z2,     z3,     l2, l3);
                lu[j*2]   = pbf(l0, l1);
                lu[j*2+1] = pbf(l2, l3);
            }
            char* ah = sm + AH_OFF;
            char* al = sm + AL_OFF;
            *(uint4*)(ah + SWZ(tid,0)) = make_uint4(hu[0],hu[1],hu[2],hu[3]);
            *(uint4*)(ah + SWZ(tid,1)) = make_uint4(hu[4],hu[5],hu[6],hu[7]);
            *(uint4*)(al + SWZ(tid,0)) = make_uint4(lu[0],lu[1],lu[2],lu[3]);
            *(uint4*)(al + SWZ(tid,1)) = make_uint4(lu[4],lu[5],lu[6],lu[7]);
        }
        __syncwarp();      // A rows are warp-private: STS -> ldmatrix visibility only

        // ---- tensor-core GEMM for this k16 chunk ----
        uint32_t ah_base = sb + AH_OFF;
        uint32_t al_base = sb + AL_OFF;
        uint32_t wh_base = sb + WH_OFF + (unsigned)c*2048u;
        uint32_t wl_base = sb + WL_OFF + (unsigned)c*2048u;
        uint32_t ahf[2][4], alf[2][4];
        ldm4(ahf[0], ah_base + aswz0);
        ldm4(ahf[1], ah_base + aswz1);
        ldm4(alf[0], al_base + aswz0);
        ldm4(alf[1], al_base + aswz1);
        #pragma unroll
        for (int np = 0; np < 4; np++){
            uint32_t bh[4], bl[4];
            ldm4(bh, wh_base + wswz[np]);
            ldm4(bl, wl_base + wswz[np]);
            #pragma unroll
            for (int s = 0; s < 2; s++){
                #pragma unroll
                for (int mt = 0; mt < 2; mt++){
                    float* d = acc[mt][np*2 + s];
                    mma16816(d, ahf[mt], bh[s*2], bh[s*2+1]);
                    mma16816(d, ahf[mt], bl[s*2], bl[s*2+1]);
                    mma16816(d, alf[mt], bh[s*2], bh[s*2+1]);
                }
            }
        }
        if (++xbuf == 3) xbuf = 0;
    }

    // ---- epilogue: bias + store ----
    // pixel p = warp*32 + mt*16 + gr (+8): image row h0+warp, col w0 + (p&31)
    const int gr = lane >> 2, tg = lane & 3;
    float* ob = out + (size_t)n*CO*HH*WW;
    #pragma unroll
    for (int mt = 0; mt < 2; mt++){
        size_t off0 = (size_t)(h0 + warp)*WW + (w0 + mt*16 + gr);
        size_t off1 = off0 + 8;
        #pragma unroll
        for (int nt = 0; nt < 8; nt++){
            int o = nt*8 + tg*2;
            float b0v = __ldg(bias + o);
            float b1v = __ldg(bias + o + 1);
            ob[(size_t)o*(HH*WW)     + off0] = acc[mt][nt][0] + b0v;
            ob[(size_t)(o+1)*(HH*WW) + off0] = acc[mt][nt][1] + b1v;
            ob[(size_t)o*(HH*WW)     + off1] = acc[mt][nt][2] + b0v;
            ob[(size_t)(o+1)*(HH*WW) + off1] = acc[mt][nt][3] + b1v;
        }
    }
}

extern "C" void kernel_launch(void* const* d_in, const int* in_sizes, int n_in,
                              void* d_out, int out_size) {
    const float* x     = (const float*)d_in[0];
    const float* theta = (const float*)d_in[1];
    const float* wts   = (const float*)d_in[2];
    const float* bias  = (const float*)d_in[3];
    float* out = (float*)d_out;

    cudaFuncSetAttribute(steered_mma,
                         cudaFuncAttributeMaxDynamicSharedMemorySize, SMEM_BYTES);
    dim3 grid(WW/TW, HH/TH, NB);
    steered_mma<<<grid, NTHREADS, SMEM_BYTES>>>(x, theta, wts, bias, out);
}

// round 11
// speedup vs baseline: 2.2092x; 1.1729x over previous
#include <cuda_runtime.h>
#include <cstdint>

#define NB 16
#define CI 64
#define CO 64
#define HH 128
#define WW 128
#define TH 8
#define TW 32
#define NTHREADS 256
#define NCHUNK 8                    // 8 channels per chunk (k32)

// staged x tile: per channel 10 rows x 40 floats ([w0-4, w0+36))
#define XROW 40
#define XS_CH (10*XROW)             // 400 floats
#define XS_CHUNK (8*XS_CH)          // 3200 floats per chunk
#define NSEG (8*10*10)              // 800 16B segments per chunk

// smem byte offsets (GEMM bases 128B-aligned)
#define XB_OFF 0                    // 3 bufs * 12800B = 38400
#define WH_OFF 38400                // W fp16: 16 k16-blocks * 64o * 32B = 32768
#define AH_OFF (WH_OFF+32768)       // 71168: A hi, 2 k16-blocks * 8192
#define AL_OFF (AH_OFF+16384)       // 87552: A lo
#define SMEM_BYTES (AL_OFF+16384)   // 103936 -> 2 CTAs/SM

// k-major 32B rows; 16B-unit XOR swizzle -> conflict-free ldmatrix/STS
#define SWZ(row, half) (((((row)*2+(half)) ^ (((row)>>2)&1)))*16)

// pack two f32 -> f16x2 (lo = a, hi = b), rn-even
__device__ __forceinline__ uint32_t pf16(float a, float b){
    uint32_t pk;
    asm("cvt.rn.f16x2.f32 %0, %1, %2;" : "=r"(pk) : "f"(b), "f"(a));
    return pk;
}
// pack + fp16 residuals
__device__ __forceinline__ uint32_t pf16r(float a, float b, float& la, float& lb){
    uint32_t pk = pf16(a, b);
    float fa, fb;
    asm("{\n\t.reg .b16 l, h;\n\tmov.b32 {l, h}, %2;\n\t"
        "cvt.f32.f16 %0, l;\n\tcvt.f32.f16 %1, h;\n\t}"
        : "=f"(fa), "=f"(fb) : "r"(pk));
    la = a - fa; lb = b - fb;
    return pk;
}
__device__ __forceinline__ void ldm4(uint32_t* r, uint32_t addr){
    asm volatile("ldmatrix.sync.aligned.m8n8.x4.shared.b16 {%0,%1,%2,%3}, [%4];"
                 : "=r"(r[0]), "=r"(r[1]), "=r"(r[2]), "=r"(r[3]) : "r"(addr));
}
__device__ __forceinline__ void mma16816(float* d, const uint32_t* a, uint32_t b0, uint32_t b1){
    asm volatile("mma.sync.aligned.m16n8k16.row.col.f32.f16.f16.f32 "
                 "{%0,%1,%2,%3}, {%4,%5,%6,%7}, {%8,%9}, {%0,%1,%2,%3};"
                 : "+f"(d[0]), "+f"(d[1]), "+f"(d[2]), "+f"(d[3])
                 : "r"(a[0]), "r"(a[1]), "r"(a[2]), "r"(a[3]), "r"(b0), "r"(b1));
}

// vectorized 16B x loader with hoisted addressing: soff<0 marks OOB (zero-fill)
__device__ __forceinline__ void load_chunk_vec(const float* __restrict__ xb, int ch, int buf,
                                               int tid, unsigned sb, const int* soff){
    unsigned dbase = sb + (unsigned)XB_OFF + (unsigned)buf*(XS_CHUNK*4u);
    const float* xc = xb + (size_t)(ch*8) * (HH*WW);
    #pragma unroll
    for (int k = 0; k < 4; k++){
        int e = tid + k*256;
        if (k < 3 || tid < (NSEG - 3*256)){
            int so = soff[k];
            const float* src = (so >= 0) ? (xc + so) : xb;
            int sz = (so >= 0) ? 16 : 0;
            asm volatile("cp.async.cg.shared.global [%0], [%1], 16, %2;"
                         :: "r"(dbase + (unsigned)e*16u), "l"(src), "r"(sz));
        }
    }
}

__global__ __launch_bounds__(NTHREADS, 2)
void steered_mma(const float* __restrict__ x, const float* __restrict__ theta,
                 const float* __restrict__ wts, const float* __restrict__ bias,
                 float* __restrict__ out)
{
    extern __shared__ float smf[];
    char* sm = (char*)smf;
    const unsigned sb = (unsigned)__cvta_generic_to_shared(sm);
    const int tid = threadIdx.x;
    const int lane = tid & 31, warp = tid >> 5;
    const int n = blockIdx.z, h0 = blockIdx.y*TH, w0 = blockIdx.x*TW;
    const float* xb = x + (size_t)n*CI*HH*WW;

    // ---- hoisted per-thread 16B-segment addressing (chunk-invariant) ----
    // e -> (channel j, row r, seg s): dst = j*400 + r*40 + s*4 floats
    int soff[4];
    #pragma unroll
    for (int k = 0; k < 4; k++){
        int e = tid + k*256;
        int j = e / 100; int rem = e - j*100;
        int r = rem / 10;  int s = rem - r*10;
        int gh = h0 - 1 + r;
        int gw = w0 - 4 + s*4;
        bool v = (e < NSEG) && ((unsigned)gh < (unsigned)HH) && ((unsigned)gw < (unsigned)WW);
        soff[k] = v ? (j*(HH*WW) + gh*WW + gw) : -1;
    }

    // prefetch x chunks 0,1 into bufs 0,1
    load_chunk_vec(xb, 0, 0, tid, sb, soff);
    asm volatile("cp.async.commit_group;" ::: "memory");
    load_chunk_vec(xb, 1, 1, tid, sb, soff);
    asm volatile("cp.async.commit_group;" ::: "memory");

    // ---- W preprocessing: wts[o][i][4] -> W[k16-block][o][k16] fp16, swizzled ----
    #pragma unroll 4
    for (int t = 0; t < 16; t++){
        int e = tid + t*256;
        int o = e & 63, i = e >> 6;
        float4 v = ((const float4*)wts)[o*64 + i];     // w[o][i][0..3]
        int cc = i >> 2, j = i & 3;
        uint32_t h0u = pf16(v.x, v.y);
        uint32_t h1u = pf16(v.z, v.w);
        int off = cc*2048 + SWZ(o, (j>>1)) + (j&1)*8;
        *(uint2*)(sm + WH_OFF + off) = make_uint2(h0u, h1u);
    }

    // ---- per-pixel harmonics (pixel: row h0+py, col w0+px) ----
    const int py = tid >> 5, px = tid & 31;
    float th = theta[((size_t)n*HH + (h0+py))*WW + (w0+px)];
    float s1, c1;
    sincosf(6.28318530717958647692f * th, &s1, &c1);
    const float c2 = 2.f*c1*c1 - 1.f, s2 = 2.f*s1*c1;
    const float cps = c1 + s1, cms = c1 - s1;
    const int ctr = (py+1)*XROW + (px+4);        // center tap in staged tile
    const float Q = 0.35355339059327376220f;     // 1/(2*sqrt(2))

    // ---- per-lane ldmatrix swizzle offsets ----
    uint32_t aswz0 = SWZ(warp*32 +      (lane & 15), (lane >> 4));
    uint32_t aswz1 = SWZ(warp*32 + 16 + (lane & 15), (lane >> 4));
    const int olc = (lane & 7) + ((lane >> 4) << 3);
    const int whalf = (lane >> 3) & 1;
    uint32_t wswz[4];
    #pragma unroll
    for (int np = 0; np < 4; np++) wswz[np] = SWZ(np*16 + olc, whalf);

    float acc[2][8][4];
    #pragma unroll
    for (int a = 0; a < 2; a++)
        #pragma unroll
        for (int b = 0; b < 8; b++)
            #pragma unroll
            for (int q = 0; q < 4; q++) acc[a][b][q] = 0.f;

    int xbuf = 0;                                  // c % 3
    for (int c = 0; c < NCHUNK; c++){
        if (c < NCHUNK-1) asm volatile("cp.async.wait_group 1;" ::: "memory");
        else              asm volatile("cp.async.wait_group 0;" ::: "memory");
        __syncthreads();   // X(c) visible everywhere; all warps done reading X(c-1)

        // prefetch X(c+2) into buf (c+2)%3
        if (c + 2 < NCHUNK){
            int wb = xbuf + 2; if (wb >= 3) wb -= 3;
            load_chunk_vec(xb, c+2, wb, tid, sb, soff);
            asm volatile("cp.async.commit_group;" ::: "memory");
        }

        // ---- build A chunk (warp-local rows): 8 ch x 4 harmonics, fp16 hi + residual ----
        {
            const float* xsb = smf + xbuf*XS_CHUNK;
            #pragma unroll
            for (int kk = 0; kk < 2; kk++){
                uint32_t hu[8], lu[8];
                #pragma unroll
                for (int jj = 0; jj < 4; jj++){
                    const float* xp = xsb + (kk*4 + jj)*XS_CH + ctr;
                    float t0=xp[-XROW-1], t1=xp[-XROW], t2=xp[-XROW+1];
                    float t3=xp[-1],      t4=xp[0],     t5=xp[1];
                    float t6=xp[XROW-1],  t7=xp[XROW],  t8=xp[XROW+1];
                    float ring = ((t0+t1)+(t2+t3)) + ((t5+t6)+(t7+t8));
                    float z2 = Q*(cps*(t8-t0) + cms*(t2-t6)) + 0.5f*(c1*(t5-t3) + s1*(t7-t1));
                    float z3 = 0.5f*(s2*((t0+t8)-(t2+t6)) + c2*((t3+t5)-(t1+t7)));
                    float l0,l1,l2,l3;
                    hu[jj*2]   = pf16r(t4,     Q*ring, l0, l1);
                    hu[jj*2+1] = pf16r(z2,     z3,     l2, l3);
                    lu[jj*2]   = pf16(l0, l1);
                    lu[jj*2+1] = pf16(l2, l3);
                }
                char* ah = sm + AH_OFF + kk*8192;
                char* al = sm + AL_OFF + kk*8192;
                *(uint4*)(ah + SWZ(tid,0)) = make_uint4(hu[0],hu[1],hu[2],hu[3]);
                *(uint4*)(ah + SWZ(tid,1)) = make_uint4(hu[4],hu[5],hu[6],hu[7]);
                *(uint4*)(al + SWZ(tid,0)) = make_uint4(lu[0],lu[1],lu[2],lu[3]);
                *(uint4*)(al + SWZ(tid,1)) = make_uint4(lu[4],lu[5],lu[6],lu[7]);
            }
        }
        __syncwarp();      // A rows are warp-private: STS -> ldmatrix visibility only

        // ---- tensor-core GEMM: 2 k16 sub-steps, 2 passes (AhWh + AlWh) ----
        #pragma unroll
        for (int kk = 0; kk < 2; kk++){
            uint32_t ah_base = sb + AH_OFF + (unsigned)kk*8192u;
            uint32_t al_base = sb + AL_OFF + (unsigned)kk*8192u;
            uint32_t wh_base = sb + WH_OFF + (unsigned)(2*c + kk)*2048u;
            uint32_t ahf[2][4], alf[2][4];
            ldm4(ahf[0], ah_base + aswz0);
            ldm4(ahf[1], ah_base + aswz1);
            ldm4(alf[0], al_base + aswz0);
            ldm4(alf[1], al_base + aswz1);
            #pragma unroll
            for (int np = 0; np < 4; np++){
                uint32_t bh[4];
                ldm4(bh, wh_base + wswz[np]);
                #pragma unroll
                for (int s = 0; s < 2; s++){
                    #pragma unroll
                    for (int mt = 0; mt < 2; mt++){
                        float* d = acc[mt][np*2 + s];
                        mma16816(d, ahf[mt], bh[s*2], bh[s*2+1]);
                        mma16816(d, alf[mt], bh[s*2], bh[s*2+1]);
                    }
                }
            }
        }
        if (++xbuf == 3) xbuf = 0;
    }

    // ---- epilogue: bias + store ----
    const int gr = lane >> 2, tg = lane & 3;
    float* ob = out + (size_t)n*CO*HH*WW;
    #pragma unroll
    for (int mt = 0; mt < 2; mt++){
        size_t off0 = (size_t)(h0 + warp)*WW + (w0 + mt*16 + gr);
        size_t off1 = off0 + 8;
        #pragma unroll
        for (int nt = 0; nt < 8; nt++){
            int o = nt*8 + tg*2;
            float b0v = __ldg(bias + o);
            float b1v = __ldg(bias + o + 1);
            ob[(size_t)o*(HH*WW)     + off0] = acc[mt][nt][0] + b0v;
            ob[(size_t)(o+1)*(HH*WW) + off0] = acc[mt][nt][1] + b1v;
            ob[(size_t)o*(HH*WW)     + off1] = acc[mt][nt][2] + b0v;
            ob[(size_t)(o+1)*(HH*WW) + off1] = acc[mt][nt][3] + b1v;
        }
    }
}

extern "C" void kernel_launch(void* const* d_in, const int* in_sizes, int n_in,
                              void* d_out, int out_size) {
    const float* x     = (const float*)d_in[0];
    const float* theta = (const float*)d_in[1];
    const float* wts   = (const float*)d_in[2];
    const float* bias  = (const float*)d_in[3];
    float* out = (float*)d_out;

    cudaFuncSetAttribute(steered_mma,
                         cudaFuncAttributeMaxDynamicSharedMemorySize, SMEM_BYTES);
    dim3 grid(WW/TW, HH/TH, NB);
    steered_mma<<<grid, NTHREADS, SMEM_BYTES>>>(x, theta, wts, bias, out);
}

// round 12
// speedup vs baseline: 2.6292x; 1.1901x over previous
#include <cuda_runtime.h>
#include <cstdint>

#define NB 16
#define CI 64
#define CO 64
#define HH 128
#define WW 128
#define TH 8
#define TW 32
#define NTHREADS 256
#define NCHUNK 8                    // 8 channels per chunk (k32)

// staged x tile: per channel 10 rows x 40 floats ([w0-4, w0+36))
#define XROW 40
#define XS_CH (10*XROW)             // 400 floats
#define XS_CHUNK (8*XS_CH)          // 3200 floats per chunk
#define NSEG (8*10*10)              // 800 16B segments per chunk

// smem byte offsets (GEMM bases 128B-aligned)
#define XB_OFF 0                    // 3 bufs * 12800B = 38400
#define WH_OFF 38400                // W fp16: 16 k16-blocks * 64o * 32B = 32768
#define AH_OFF (WH_OFF+32768)       // 71168: A fp16, 2 k16-blocks * 8192
#define SMEM_BYTES (AH_OFF+16384)   // 87552 -> 2 CTAs/SM

// k-major 32B rows; 16B-unit XOR swizzle -> conflict-free ldmatrix/STS
#define SWZ(row, half) (((((row)*2+(half)) ^ (((row)>>2)&1)))*16)

// pack two f32 -> f16x2 (lo = a, hi = b), rn-even
__device__ __forceinline__ uint32_t pf16(float a, float b){
    uint32_t pk;
    asm("cvt.rn.f16x2.f32 %0, %1, %2;" : "=r"(pk) : "f"(b), "f"(a));
    return pk;
}
__device__ __forceinline__ void ldm4(uint32_t* r, uint32_t addr){
    asm volatile("ldmatrix.sync.aligned.m8n8.x4.shared.b16 {%0,%1,%2,%3}, [%4];"
                 : "=r"(r[0]), "=r"(r[1]), "=r"(r[2]), "=r"(r[3]) : "r"(addr));
}
__device__ __forceinline__ void mma16816(float* d, const uint32_t* a, uint32_t b0, uint32_t b1){
    asm volatile("mma.sync.aligned.m16n8k16.row.col.f32.f16.f16.f32 "
                 "{%0,%1,%2,%3}, {%4,%5,%6,%7}, {%8,%9}, {%0,%1,%2,%3};"
                 : "+f"(d[0]), "+f"(d[1]), "+f"(d[2]), "+f"(d[3])
                 : "r"(a[0]), "r"(a[1]), "r"(a[2]), "r"(a[3]), "r"(b0), "r"(b1));
}

// vectorized 16B x loader with hoisted addressing: soff<0 marks OOB (zero-fill)
__device__ __forceinline__ void load_chunk_vec(const float* __restrict__ xb, int ch, int buf,
                                               int tid, unsigned sb, const int* soff){
    unsigned dbase = sb + (unsigned)XB_OFF + (unsigned)buf*(XS_CHUNK*4u);
    const float* xc = xb + (size_t)(ch*8) * (HH*WW);
    #pragma unroll
    for (int k = 0; k < 4; k++){
        int e = tid + k*256;
        if (k < 3 || tid < (NSEG - 3*256)){
            int so = soff[k];
            const float* src = (so >= 0) ? (xc + so) : xb;
            int sz = (so >= 0) ? 16 : 0;
            asm volatile("cp.async.cg.shared.global [%0], [%1], 16, %2;"
                         :: "r"(dbase + (unsigned)e*16u), "l"(src), "r"(sz));
        }
    }
}

__global__ __launch_bounds__(NTHREADS, 2)
void steered_mma(const float* __restrict__ x, const float* __restrict__ theta,
                 const float* __restrict__ wts, const float* __restrict__ bias,
                 float* __restrict__ out)
{
    extern __shared__ float smf[];
    char* sm = (char*)smf;
    const unsigned sb = (unsigned)__cvta_generic_to_shared(sm);
    const int tid = threadIdx.x;
    const int lane = tid & 31, warp = tid >> 5;
    const int n = blockIdx.z, h0 = blockIdx.y*TH, w0 = blockIdx.x*TW;
    const float* xb = x + (size_t)n*CI*HH*WW;

    // ---- hoisted per-thread 16B-segment addressing (chunk-invariant) ----
    int soff[4];
    #pragma unroll
    for (int k = 0; k < 4; k++){
        int e = tid + k*256;
        int j = e / 100; int rem = e - j*100;
        int r = rem / 10;  int s = rem - r*10;
        int gh = h0 - 1 + r;
        int gw = w0 - 4 + s*4;
        bool v = (e < NSEG) && ((unsigned)gh < (unsigned)HH) && ((unsigned)gw < (unsigned)WW);
        soff[k] = v ? (j*(HH*WW) + gh*WW + gw) : -1;
    }

    // prefetch x chunks 0,1 into bufs 0,1
    load_chunk_vec(xb, 0, 0, tid, sb, soff);
    asm volatile("cp.async.commit_group;" ::: "memory");
    load_chunk_vec(xb, 1, 1, tid, sb, soff);
    asm volatile("cp.async.commit_group;" ::: "memory");

    // ---- W preprocessing: wts[o][i][4] -> W[k16-block][o][k16] fp16, swizzled ----
    #pragma unroll 4
    for (int t = 0; t < 16; t++){
        int e = tid + t*256;
        int o = e & 63, i = e >> 6;
        float4 v = ((const float4*)wts)[o*64 + i];     // w[o][i][0..3]
        int cc = i >> 2, j = i & 3;
        uint32_t h0u = pf16(v.x, v.y);
        uint32_t h1u = pf16(v.z, v.w);
        int off = cc*2048 + SWZ(o, (j>>1)) + (j&1)*8;
        *(uint2*)(sm + WH_OFF + off) = make_uint2(h0u, h1u);
    }

    // ---- per-pixel harmonics (pixel: row h0+py, col w0+px) ----
    const int py = tid >> 5, px = tid & 31;
    float th = theta[((size_t)n*HH + (h0+py))*WW + (w0+px)];
    float s1, c1;
    sincosf(6.28318530717958647692f * th, &s1, &c1);
    const float c2 = 2.f*c1*c1 - 1.f, s2 = 2.f*s1*c1;
    const float cps = c1 + s1, cms = c1 - s1;
    const int ctr = (py+1)*XROW + (px+4);        // center tap in staged tile
    const float Q = 0.35355339059327376220f;     // 1/(2*sqrt(2))

    // ---- per-lane ldmatrix swizzle offsets ----
    uint32_t aswz0 = SWZ(warp*32 +      (lane & 15), (lane >> 4));
    uint32_t aswz1 = SWZ(warp*32 + 16 + (lane & 15), (lane >> 4));
    const int olc = (lane & 7) + ((lane >> 4) << 3);
    const int whalf = (lane >> 3) & 1;
    uint32_t wswz[4];
    #pragma unroll
    for (int np = 0; np < 4; np++) wswz[np] = SWZ(np*16 + olc, whalf);

    float acc[2][8][4];
    #pragma unroll
    for (int a = 0; a < 2; a++)
        #pragma unroll
        for (int b = 0; b < 8; b++)
            #pragma unroll
            for (int q = 0; q < 4; q++) acc[a][b][q] = 0.f;

    int xbuf = 0;                                  // c % 3
    for (int c = 0; c < NCHUNK; c++){
        if (c < NCHUNK-1) asm volatile("cp.async.wait_group 1;" ::: "memory");
        else              asm volatile("cp.async.wait_group 0;" ::: "memory");
        __syncthreads();   // X(c) visible everywhere; all warps done reading X(c-1)

        // prefetch X(c+2) into buf (c+2)%3
        if (c + 2 < NCHUNK){
            int wb = xbuf + 2; if (wb >= 3) wb -= 3;
            load_chunk_vec(xb, c+2, wb, tid, sb, soff);
            asm volatile("cp.async.commit_group;" ::: "memory");
        }

        // ---- build A chunk (warp-local rows): 8 ch x 4 harmonics, fp16 ----
        {
            const float* xsb = smf + xbuf*XS_CHUNK;
            #pragma unroll
            for (int kk = 0; kk < 2; kk++){
                uint32_t hu[8];
                #pragma unroll
                for (int jj = 0; jj < 4; jj++){
                    const float* xp = xsb + (kk*4 + jj)*XS_CH + ctr;
                    float t0=xp[-XROW-1], t1=xp[-XROW], t2=xp[-XROW+1];
                    float t3=xp[-1],      t4=xp[0],     t5=xp[1];
                    float t6=xp[XROW-1],  t7=xp[XROW],  t8=xp[XROW+1];
                    float ring = ((t0+t1)+(t2+t3)) + ((t5+t6)+(t7+t8));
                    float z2 = Q*(cps*(t8-t0) + cms*(t2-t6)) + 0.5f*(c1*(t5-t3) + s1*(t7-t1));
                    float z3 = 0.5f*(s2*((t0+t8)-(t2+t6)) + c2*((t3+t5)-(t1+t7)));
                    hu[jj*2]   = pf16(t4, Q*ring);
                    hu[jj*2+1] = pf16(z2, z3);
                }
                char* ah = sm + AH_OFF + kk*8192;
                *(uint4*)(ah + SWZ(tid,0)) = make_uint4(hu[0],hu[1],hu[2],hu[3]);
                *(uint4*)(ah + SWZ(tid,1)) = make_uint4(hu[4],hu[5],hu[6],hu[7]);
            }
        }
        __syncwarp();      // A rows are warp-private: STS -> ldmatrix visibility only

        // ---- tensor-core GEMM: 2 k16 sub-steps, single fp16 pass ----
        #pragma unroll
        for (int kk = 0; kk < 2; kk++){
            uint32_t ah_base = sb + AH_OFF + (unsigned)kk*8192u;
            uint32_t wh_base = sb + WH_OFF + (unsigned)(2*c + kk)*2048u;
            uint32_t ahf[2][4];
            ldm4(ahf[0], ah_base + aswz0);
            ldm4(ahf[1], ah_base + aswz1);
            #pragma unroll
            for (int np = 0; np < 4; np++){
                uint32_t bh[4];
                ldm4(bh, wh_base + wswz[np]);
                #pragma unroll
                for (int s = 0; s < 2; s++){
                    #pragma unroll
                    for (int mt = 0; mt < 2; mt++){
                        float* d = acc[mt][np*2 + s];
                        mma16816(d, ahf[mt], bh[s*2], bh[s*2+1]);
                    }
                }
            }
        }
        if (++xbuf == 3) xbuf = 0;
    }

    // ---- epilogue: bias + store ----
    const int gr = lane >> 2, tg = lane & 3;
    float* ob = out + (size_t)n*CO*HH*WW;
    #pragma unroll
    for (int mt = 0; mt < 2; mt++){
        size_t off0 = (size_t)(h0 + warp)*WW + (w0 + mt*16 + gr);
        size_t off1 = off0 + 8;
        #pragma unroll
        for (int nt = 0; nt < 8; nt++){
            int o = nt*8 + tg*2;
            float b0v = __ldg(bias + o);
            float b1v = __ldg(bias + o + 1);
            ob[(size_t)o*(HH*WW)     + off0] = acc[mt][nt][0] + b0v;
            ob[(size_t)(o+1)*(HH*WW) + off0] = acc[mt][nt][1] + b1v;
            ob[(size_t)o*(HH*WW)     + off1] = acc[mt][nt][2] + b0v;
            ob[(size_t)(o+1)*(HH*WW) + off1] = acc[mt][nt][3] + b1v;
        }
    }
}

extern "C" void kernel_launch(void* const* d_in, const int* in_sizes, int n_in,
                              void* d_out, int out_size) {
    const float* x     = (const float*)d_in[0];
    const float* theta = (const float*)d_in[1];
    const float* wts   = (const float*)d_in[2];
    const float* bias  = (const float*)d_in[3];
    float* out = (float*)d_out;

    cudaFuncSetAttribute(steered_mma,
                         cudaFuncAttributeMaxDynamicSharedMemorySize, SMEM_BYTES);
    dim3 grid(WW/TW, HH/TH, NB);
    steered_mma<<<grid, NTHREADS, SMEM_BYTES>>>(x, theta, wts, bias, out);
}

// round 13
// speedup vs baseline: 2.6918x; 1.0238x over previous
#include <cuda_runtime.h>
#include <cstdint>

#define NB 16
#define CI 64
#define CO 64
#define HH 128
#define WW 128
#define TH 8
#define TW 32
#define NTHREADS 256
#define NCHUNK 8                    // 8 channels per chunk (k32)

// staged x tile: per channel 10 rows x 40 floats ([w0-4, w0+36))
#define XROW 40
#define XS_CH (10*XROW)             // 400 floats
#define XS_CHUNK (8*XS_CH)          // 3200 floats per chunk
#define NSEG (8*10*10)              // 800 16B segments per chunk

// smem byte offsets (GEMM bases 128B-aligned)
#define XB_OFF 0                    // 3 bufs * 12800B = 38400
#define WH_OFF 38400                // W fp16: 16 k16-blocks * 64o * 32B = 32768
#define AH_OFF (WH_OFF+32768)       // 71168: A fp16, 2 chunk-bufs * 16384
#define SMEM_BYTES (AH_OFF+32768)   // 103936 -> 2 CTAs/SM

// k-major 32B rows; 16B-unit XOR swizzle -> conflict-free ldmatrix/STS
#define SWZ(row, half) (((((row)*2+(half)) ^ (((row)>>2)&1)))*16)

// pack two f32 -> f16x2 (lo = a, hi = b), rn-even
__device__ __forceinline__ uint32_t pf16(float a, float b){
    uint32_t pk;
    asm("cvt.rn.f16x2.f32 %0, %1, %2;" : "=r"(pk) : "f"(b), "f"(a));
    return pk;
}
__device__ __forceinline__ void ldm4(uint32_t* r, uint32_t addr){
    asm volatile("ldmatrix.sync.aligned.m8n8.x4.shared.b16 {%0,%1,%2,%3}, [%4];"
                 : "=r"(r[0]), "=r"(r[1]), "=r"(r[2]), "=r"(r[3]) : "r"(addr));
}
__device__ __forceinline__ void mma16816(float* d, const uint32_t* a, uint32_t b0, uint32_t b1){
    asm volatile("mma.sync.aligned.m16n8k16.row.col.f32.f16.f16.f32 "
                 "{%0,%1,%2,%3}, {%4,%5,%6,%7}, {%8,%9}, {%0,%1,%2,%3};"
                 : "+f"(d[0]), "+f"(d[1]), "+f"(d[2]), "+f"(d[3])
                 : "r"(a[0]), "r"(a[1]), "r"(a[2]), "r"(a[3]), "r"(b0), "r"(b1));
}

// vectorized 16B x loader with hoisted addressing: soff<0 marks OOB (zero-fill)
__device__ __forceinline__ void load_chunk_vec(const float* __restrict__ xb, int ch, int buf,
                                               int tid, unsigned sb, const int* soff){
    unsigned dbase = sb + (unsigned)XB_OFF + (unsigned)buf*(XS_CHUNK*4u);
    const float* xc = xb + (size_t)(ch*8) * (HH*WW);
    #pragma unroll
    for (int k = 0; k < 4; k++){
        int e = tid + k*256;
        if (k < 3 || tid < (NSEG - 3*256)){
            int so = soff[k];
            const float* src = (so >= 0) ? (xc + so) : xb;
            int sz = (so >= 0) ? 16 : 0;
            asm volatile("cp.async.cg.shared.global [%0], [%1], 16, %2;"
                         :: "r"(dbase + (unsigned)e*16u), "l"(src), "r"(sz));
        }
    }
}

// build A chunk (warp-local row tid): 8 ch x 4 harmonics -> fp16, swizzled STS
__device__ __forceinline__ void build_A(char* sm, const float* xsb, int abuf_off, int tid, int ctr,
                                        float c1, float s1, float c2, float s2,
                                        float cps, float cms){
    const float Q = 0.35355339059327376220f;     // 1/(2*sqrt(2))
    #pragma unroll
    for (int kk = 0; kk < 2; kk++){
        uint32_t hu[8];
        #pragma unroll
        for (int jj = 0; jj < 4; jj++){
            const float* xp = xsb + (kk*4 + jj)*XS_CH + ctr;
            float t0=xp[-XROW-1], t1=xp[-XROW], t2=xp[-XROW+1];
            float t3=xp[-1],      t4=xp[0],     t5=xp[1];
            float t6=xp[XROW-1],  t7=xp[XROW],  t8=xp[XROW+1];
            float ring = ((t0+t1)+(t2+t3)) + ((t5+t6)+(t7+t8));
            float z2 = Q*(cps*(t8-t0) + cms*(t2-t6)) + 0.5f*(c1*(t5-t3) + s1*(t7-t1));
            float z3 = 0.5f*(s2*((t0+t8)-(t2+t6)) + c2*((t3+t5)-(t1+t7)));
            hu[jj*2]   = pf16(t4, Q*ring);
            hu[jj*2+1] = pf16(z2, z3);
        }
        char* ah = sm + AH_OFF + abuf_off + kk*8192;
        *(uint4*)(ah + SWZ(tid,0)) = make_uint4(hu[0],hu[1],hu[2],hu[3]);
        *(uint4*)(ah + SWZ(tid,1)) = make_uint4(hu[4],hu[5],hu[6],hu[7]);
    }
}

__global__ __launch_bounds__(NTHREADS, 2)
void steered_mma(const float* __restrict__ x, const float* __restrict__ theta,
                 const float* __restrict__ wts, const float* __restrict__ bias,
                 float* __restrict__ out)
{
    extern __shared__ float smf[];
    char* sm = (char*)smf;
    const unsigned sb = (unsigned)__cvta_generic_to_shared(sm);
    const int tid = threadIdx.x;
    const int lane = tid & 31, warp = tid >> 5;
    const int n = blockIdx.z, h0 = blockIdx.y*TH, w0 = blockIdx.x*TW;
    const float* xb = x + (size_t)n*CI*HH*WW;

    // ---- hoisted per-thread 16B-segment addressing (chunk-invariant) ----
    int soff[4];
    #pragma unroll
    for (int k = 0; k < 4; k++){
        int e = tid + k*256;
        int j = e / 100; int rem = e - j*100;
        int r = rem / 10;  int s = rem - r*10;
        int gh = h0 - 1 + r;
        int gw = w0 - 4 + s*4;
        bool v = (e < NSEG) && ((unsigned)gh < (unsigned)HH) && ((unsigned)gw < (unsigned)WW);
        soff[k] = v ? (j*(HH*WW) + gh*WW + gw) : -1;
    }

    // prefetch x chunks 0,1 into bufs 0,1
    load_chunk_vec(xb, 0, 0, tid, sb, soff);
    asm volatile("cp.async.commit_group;" ::: "memory");
    load_chunk_vec(xb, 1, 1, tid, sb, soff);
    asm volatile("cp.async.commit_group;" ::: "memory");

    // ---- W preprocessing: wts[o][i][4] -> W[k16-block][o][k16] fp16, swizzled ----
    #pragma unroll 4
    for (int t = 0; t < 16; t++){
        int e = tid + t*256;
        int o = e & 63, i = e >> 6;
        float4 v = ((const float4*)wts)[o*64 + i];     // w[o][i][0..3]
        int cc = i >> 2, j = i & 3;
        uint32_t h0u = pf16(v.x, v.y);
        uint32_t h1u = pf16(v.z, v.w);
        int off = cc*2048 + SWZ(o, (j>>1)) + (j&1)*8;
        *(uint2*)(sm + WH_OFF + off) = make_uint2(h0u, h1u);
    }

    // ---- per-pixel harmonics (pixel: row h0+py, col w0+px) ----
    const int py = tid >> 5, px = tid & 31;
    float th = theta[((size_t)n*HH + (h0+py))*WW + (w0+px)];
    float s1, c1;
    sincosf(6.28318530717958647692f * th, &s1, &c1);
    const float c2 = 2.f*c1*c1 - 1.f, s2 = 2.f*s1*c1;
    const float cps = c1 + s1, cms = c1 - s1;
    const int ctr = (py+1)*XROW + (px+4);        // center tap in staged tile

    // ---- per-lane ldmatrix swizzle offsets ----
    uint32_t aswz0 = SWZ(warp*32 +      (lane & 15), (lane >> 4));
    uint32_t aswz1 = SWZ(warp*32 + 16 + (lane & 15), (lane >> 4));
    const int olc = (lane & 7) + ((lane >> 4) << 3);
    const int whalf = (lane >> 3) & 1;
    uint32_t wswz[4];
    #pragma unroll
    for (int np = 0; np < 4; np++) wswz[np] = SWZ(np*16 + olc, whalf);

    float acc[2][8][4];
    #pragma unroll
    for (int a = 0; a < 2; a++)
        #pragma unroll
        for (int b = 0; b < 8; b++)
            #pragma unroll
            for (int q = 0; q < 4; q++) acc[a][b][q] = 0.f;

    // ---- pipeline prologue: X(0) ready -> build A(0) into buf 0 ----
    asm volatile("cp.async.wait_group 1;" ::: "memory");   // X(0) complete
    __syncthreads();                                       // X(0) visible CTA-wide
    build_A(sm, smf + 0*XS_CHUNK, 0, tid, ctr, c1, s1, c2, s2, cps, cms);
    load_chunk_vec(xb, 2, 2, tid, sb, soff);               // prefetch X(2) -> buf 2
    asm volatile("cp.async.commit_group;" ::: "memory");

    for (int c = 0; c < NCHUNK; c++){
        __syncwarp();            // A(c) STS (warp-private rows) -> ldmatrix visibility

        const unsigned abuf = sb + AH_OFF + (unsigned)(c & 1)*16384u;
        uint32_t ahf0[2][4];     // kk=0 fragments, loaded before the overlapped build
        ldm4(ahf0[0], abuf + aswz0);
        ldm4(ahf0[1], abuf + aswz1);

        if (c < NCHUNK-1){
            // make X(c+1) visible; prefetch X(c+3); build A(c+1) (overlaps GEMM below)
            if (c < NCHUNK-2) asm volatile("cp.async.wait_group 1;" ::: "memory");
            else              asm volatile("cp.async.wait_group 0;" ::: "memory");
            __syncthreads();     // X(c+1) visible; all reads of X-buf c%3 retired
            if (c + 3 < NCHUNK){
                int wb = c % 3;  // (c+3)%3
                load_chunk_vec(xb, c+3, wb, tid, sb, soff);
                asm volatile("cp.async.commit_group;" ::: "memory");
            }
            build_A(sm, smf + ((c+1)%3)*XS_CHUNK, ((c+1)&1)*16384, tid, ctr,
                    c1, s1, c2, s2, cps, cms);
        }

        // ---- GEMM kk=0 (frags preloaded; W ldm independent of build) ----
        {
            uint32_t wh_base = sb + WH_OFF + (unsigned)(2*c)*2048u;
            #pragma unroll
            for (int np = 0; np < 4; np++){
                uint32_t bh[4];
                ldm4(bh, wh_base + wswz[np]);
                #pragma unroll
                for (int s = 0; s < 2; s++){
                    #pragma unroll
                    for (int mt = 0; mt < 2; mt++)
                        mma16816(acc[mt][np*2 + s], ahf0[mt], bh[s*2], bh[s*2+1]);
                }
            }
        }
        // ---- GEMM kk=1 (A buf c&1 untouched by build of (c+1)&1) ----
        {
            uint32_t ahf1[2][4];
            ldm4(ahf1[0], abuf + 8192u + aswz0);
            ldm4(ahf1[1], abuf + 8192u + aswz1);
            uint32_t wh_base = sb + WH_OFF + (unsigned)(2*c + 1)*2048u;
            #pragma unroll
            for (int np = 0; np < 4; np++){
                uint32_t bh[4];
                ldm4(bh, wh_base + wswz[np]);
                #pragma unroll
                for (int s = 0; s < 2; s++){
                    #pragma unroll
                    for (int mt = 0; mt < 2; mt++)
                        mma16816(acc[mt][np*2 + s], ahf1[mt], bh[s*2], bh[s*2+1]);
                }
            }
        }
    }

    // ---- epilogue: bias + store ----
    const int gr = lane >> 2, tg = lane & 3;
    float* ob = out + (size_t)n*CO*HH*WW;
    #pragma unroll
    for (int mt = 0; mt < 2; mt++){
        size_t off0 = (size_t)(h0 + warp)*WW + (w0 + mt*16 + gr);
        size_t off1 = off0 + 8;
        #pragma unroll
        for (int nt = 0; nt < 8; nt++){
            int o = nt*8 + tg*2;
            float b0v = __ldg(bias + o);
            float b1v = __ldg(bias + o + 1);
            ob[(size_t)o*(HH*WW)     + off0] = acc[mt][nt][0] + b0v;
            ob[(size_t)(o+1)*(HH*WW) + off0] = acc[mt][nt][1] + b1v;
            ob[(size_t)o*(HH*WW)     + off1] = acc[mt][nt][2] + b0v;
            ob[(size_t)(o+1)*(HH*WW) + off1] = acc[mt][nt][3] + b1v;
        }
    }
}

extern "C" void kernel_launch(void* const* d_in, const int* in_sizes, int n_in,
                              void* d_out, int out_size) {
    const float* x     = (const float*)d_in[0];
    const float* theta = (const float*)d_in[1];
    const float* wts   = (const float*)d_in[2];
    const float* bias  = (const float*)d_in[3];
    float* out = (float*)d_out;

    cudaFuncSetAttribute(steered_mma,
                         cudaFuncAttributeMaxDynamicSharedMemorySize, SMEM_BYTES);
    dim3 grid(WW/TW, HH/TH, NB);
    steered_mma<<<grid, NTHREADS, SMEM_BYTES>>>(x, theta, wts, bias, out);
}